// round 4
// baseline (speedup 1.0000x reference)
#include <cuda_runtime.h>
#include <math.h>

// ---------------- problem constants -----------------------------------------
#define R_ROIS 2000
#define NOBJ   21
#define HFE    38
#define WFE    50
#define D1     25088        // 512*7*7
#define DH     4096
#define DH4    (DH/4)       // 1024 float4 per row
#define NACT   27
#define HUMAN_LBL 14

#define SPLIT1 256
#define ROWS1  (D1/SPLIT1)  // 98 rows per block, contiguous 1.6MB slab
#define SPLIT2 32
#define ROWS2  (DH/SPLIT2)  // 128
#define PREF_BLKS 64        // W2 prefetch blocks appended to gemv1 grid
#define PREF_F4_PER_BLK ((DH*DH/4)/PREF_BLKS)   // 262144/... = 65536 float4 (1 MiB)
#define PREF_F4_PER_THR (PREF_F4_PER_BLK/256)   // 256 float4

// ---------------- device scratch --------------------------------------------
__device__ float  g_logZ[R_ROIS];
__device__ float  g_kept[20][4];
__device__ float  g_hbox[4];
__device__ float  g_feat[D1];
__device__ float4 g_part1[SPLIT1 * DH4];   // [split][j] as floats
__device__ float4 g_part2[SPLIT2 * DH4];
__device__ float  g_loc[4];
__device__ float  g_sink[PREF_BLKS * 256]; // prefetch DCE guard (never read)

// ---------------------------------------------------------------------------
// Kernel 0: per-roi softmax log-normalizer
// ---------------------------------------------------------------------------
__global__ void k_softprep(const float* __restrict__ scores)
{
    const int r = blockIdx.x * blockDim.x + threadIdx.x;
    if (r >= R_ROIS) return;
    const float* s = scores + r * NOBJ;
    float mx = s[0];
    #pragma unroll
    for (int j = 1; j < NOBJ; j++) mx = fmaxf(mx, s[j]);
    float sum = 0.0f;
    #pragma unroll
    for (int j = 0; j < NOBJ; j++) sum += expf(s[j] - mx);
    g_logZ[r] = mx + logf(sum);
}

// ---------------------------------------------------------------------------
// Kernel 1: per-class argmax (NMS_T=0 => top-1 per class) + box decode
// ---------------------------------------------------------------------------
__global__ void k_select(const float* __restrict__ scores,
                         const float* __restrict__ off,
                         const float* __restrict__ rois,
                         const int*   __restrict__ imgshape)
{
    const int l   = blockIdx.x;
    const int cls = l + 1;

    float best  = -1e30f;
    int   bestr = 0x7fffffff;
    for (int r = threadIdx.x; r < R_ROIS; r += blockDim.x) {
        const float t = scores[r * NOBJ + cls] - g_logZ[r];
        if (t > best) { best = t; bestr = r; }
    }

    __shared__ float sb[256];
    __shared__ int   si[256];
    sb[threadIdx.x] = best;
    si[threadIdx.x] = bestr;
    __syncthreads();
    for (int st = blockDim.x >> 1; st > 0; st >>= 1) {
        if (threadIdx.x < st) {
            float ob = sb[threadIdx.x + st];
            int   oi = si[threadIdx.x + st];
            if (ob > sb[threadIdx.x] ||
                (ob == sb[threadIdx.x] && oi < si[threadIdx.x])) {
                sb[threadIdx.x] = ob; si[threadIdx.x] = oi;
            }
        }
        __syncthreads();
    }

    if (threadIdx.x == 0) {
        const int r = si[0];
        const float img0 = (float)imgshape[0];
        const float img1 = (float)imgshape[1];
        const float sy = (float)HFE / img0;
        const float sx = (float)WFE / img1;
        const float y1 = rois[r * 4 + 0] * sy;
        const float x1 = rois[r * 4 + 1] * sx;
        const float y2 = rois[r * 4 + 2] * sy;
        const float x2 = rois[r * 4 + 3] * sx;
        const float dy = off[r * (NOBJ * 4) + cls * 4 + 0] * 0.1f;
        const float dx = off[r * (NOBJ * 4) + cls * 4 + 1] * 0.1f;
        const float dh = off[r * (NOBJ * 4) + cls * 4 + 2] * 0.2f;
        const float dw = off[r * (NOBJ * 4) + cls * 4 + 3] * 0.2f;
        const float h  = y2 - y1, w = x2 - x1;
        const float cy = y1 + 0.5f * h, cx = x1 + 0.5f * w;
        const float cy2 = dy * h + cy, cx2 = dx * w + cx;
        const float h2 = expf(dh) * h, w2 = expf(dw) * w;
        float by1 = fminf(fmaxf(cy2 - 0.5f * h2, 0.0f), (float)HFE);
        float bx1 = fminf(fmaxf(cx2 - 0.5f * w2, 0.0f), (float)WFE);
        float by2 = fminf(fmaxf(cy2 + 0.5f * h2, 0.0f), (float)HFE);
        float bx2 = fminf(fmaxf(cx2 + 0.5f * w2, 0.0f), (float)WFE);
        g_kept[l][0] = by1; g_kept[l][1] = bx1;
        g_kept[l][2] = by2; g_kept[l][3] = bx2;
        if (l == HUMAN_LBL) {
            g_hbox[0] = by1; g_hbox[1] = bx1;
            g_hbox[2] = by2; g_hbox[3] = bx2;
        }
    }
}

// ---------------------------------------------------------------------------
// Kernel 2: chainer-style RoIPooling2D on the human box
// ---------------------------------------------------------------------------
__global__ void k_roipool(const float* __restrict__ x)
{
    const int idx = blockIdx.x * blockDim.x + threadIdx.x;
    if (idx >= D1) return;
    const int c  = idx / 49;
    const int ph = (idx % 49) / 7;
    const int pw = idx % 7;

    const float y1 = g_hbox[0], x1 = g_hbox[1], y2 = g_hbox[2], x2 = g_hbox[3];
    const int xmin = (int)rintf(x1 * 0.0625f);
    const int ymin = (int)rintf(y1 * 0.0625f);
    const int xmax = (int)rintf(x2 * 0.0625f);
    const int ymax = (int)rintf(y2 * 0.0625f);
    const float rw = (float)max(xmax - xmin + 1, 1);
    const float rh = (float)max(ymax - ymin + 1, 1);

    int hs = ymin + (int)floorf((float)ph * rh / 7.0f);
    int he = ymin + (int)ceilf((float)(ph + 1) * rh / 7.0f);
    int ws = xmin + (int)floorf((float)pw * rw / 7.0f);
    int we = xmin + (int)ceilf((float)(pw + 1) * rw / 7.0f);
    hs = min(max(hs, 0), HFE); he = min(max(he, 0), HFE);
    ws = min(max(ws, 0), WFE); we = min(max(we, 0), WFE);

    float m = -1e30f;
    for (int yy = hs; yy < he; yy++)
        for (int xx = ws; xx < we; xx++)
            m = fmaxf(m, x[c * (HFE * WFE) + yy * WFE + xx]);
    g_feat[idx] = (hs < he && ws < we) ? ((m <= -0.5e30f) ? 0.0f : m) : 0.0f;
}

// ---------------------------------------------------------------------------
// Kernel 3: GEMV1, contiguous-slab split-K.
// Block b < SPLIT1: owns rows [b*98, b*98+98) of W1 — a contiguous 1.6MB slab.
//   Thread t accumulates 4 float4 outputs (columns t+256q). Every row read is
//   one coalesced 16KB burst; consecutive rows are contiguous in DRAM.
// Block b >= SPLIT1: streams 1MiB of W2 into L2 (evict-normal) while W1 uses
//   __ldcs (evict-first) so W2 survives for gemv2.
// ---------------------------------------------------------------------------
__global__ void k_gemv1(const float4* __restrict__ W1,
                        const float4* __restrict__ W2)
{
    const int b = blockIdx.x;
    const int t = threadIdx.x;

    if (b < SPLIT1) {
        const int i0 = b * ROWS1;

        __shared__ float sf[ROWS1];
        if (t < ROWS1) sf[t] = g_feat[i0 + t];
        __syncthreads();

        float4 a0 = make_float4(0.f,0.f,0.f,0.f);
        float4 a1 = a0, a2 = a0, a3 = a0;
        const float4* __restrict__ w = W1 + (size_t)i0 * DH4;

        #pragma unroll 2
        for (int i = 0; i < ROWS1; i++) {
            const size_t rb = (size_t)i * DH4;
            const float4 v0 = __ldcs(&w[rb + t]);
            const float4 v1 = __ldcs(&w[rb + t + 256]);
            const float4 v2 = __ldcs(&w[rb + t + 512]);
            const float4 v3 = __ldcs(&w[rb + t + 768]);
            const float  s  = sf[i];
            a0.x += s*v0.x; a0.y += s*v0.y; a0.z += s*v0.z; a0.w += s*v0.w;
            a1.x += s*v1.x; a1.y += s*v1.y; a1.z += s*v1.z; a1.w += s*v1.w;
            a2.x += s*v2.x; a2.y += s*v2.y; a2.z += s*v2.z; a2.w += s*v2.w;
            a3.x += s*v3.x; a3.y += s*v3.y; a3.z += s*v3.z; a3.w += s*v3.w;
        }
        g_part1[b * DH4 + t      ] = a0;
        g_part1[b * DH4 + t + 256] = a1;
        g_part1[b * DH4 + t + 512] = a2;
        g_part1[b * DH4 + t + 768] = a3;
    } else {
        // W2 prefetch into L2: 64 blocks x 1 MiB contiguous each
        const int pid = b - SPLIT1;
        const size_t base = (size_t)pid * PREF_F4_PER_BLK + t;
        float acc = 0.0f;
        #pragma unroll 8
        for (int i = 0; i < PREF_F4_PER_THR; i++) {
            const float4 v = __ldg(&W2[base + (size_t)i * 256]);
            acc += v.x + v.y + v.z + v.w;
        }
        g_sink[pid * 256 + t] = acc;   // DCE guard, never read
    }
}

// ---------------------------------------------------------------------------
// Kernel 4: GEMV2 with fused reduce1 prologue.
// grid (4, SPLIT2), 256 threads. Prologue: rebuild h1[i0..i0+128) from part1
// (L2-resident). Main: W2 (L2-resident from prefetch) column dot.
// ---------------------------------------------------------------------------
__global__ void k_gemv2(const float4* __restrict__ W2,
                        const float*  __restrict__ b1)
{
    const int t  = threadIdx.x;
    const int i0 = blockIdx.y * ROWS2;
    const float* p1 = (const float*)g_part1;   // [SPLIT1][DH]

    __shared__ float sh[2][ROWS2];
    __shared__ float h1s[ROWS2];

    // prologue: h1 slice
    {
        const int jj   = t & 127;
        const int half = t >> 7;
        float s = 0.0f;
        #pragma unroll 8
        for (int k = 0; k < SPLIT1 / 2; k++)
            s += p1[(size_t)(half * (SPLIT1 / 2) + k) * DH + i0 + jj];
        sh[half][jj] = s;
    }
    __syncthreads();
    if (t < ROWS2)
        h1s[t] = fmaxf(sh[0][t] + sh[1][t] + b1[i0 + t], 0.0f);
    __syncthreads();

    // main: columns j4 = bx*256 + t
    const int j4 = blockIdx.x * 256 + t;
    float4 acc = make_float4(0.f,0.f,0.f,0.f);
    const float4* __restrict__ w = W2 + (size_t)i0 * DH4 + j4;
    #pragma unroll 8
    for (int i = 0; i < ROWS2; i++) {
        const float4 v = __ldg(&w[(size_t)i * DH4]);
        const float  s = h1s[i];
        acc.x += s*v.x; acc.y += s*v.y; acc.z += s*v.z; acc.w += s*v.w;
    }
    g_part2[blockIdx.y * DH4 + j4] = acc;
}

// ---------------------------------------------------------------------------
// Kernel 5: heads with fused reduce2. 31 blocks, 256 threads.
// Each block rebuilds fc7 (4096) in smem from part2, then does its dot.
// ---------------------------------------------------------------------------
__global__ void k_heads(const float* __restrict__ Wloc, const float* __restrict__ bloc,
                        const float* __restrict__ Wact, const float* __restrict__ bact,
                        const float* __restrict__ b2,   float* __restrict__ out)
{
    const int o = blockIdx.x;   // 0..30
    const int t = threadIdx.x;
    const float* p2 = (const float*)g_part2;   // [SPLIT2][DH]

    __shared__ float fc7s[DH];
    #pragma unroll
    for (int q = 0; q < DH / 256; q++) {        // 16 columns per thread
        const int jj = q * 256 + t;
        float s = b2[jj];
        #pragma unroll 8
        for (int k = 0; k < SPLIT2; k++)
            s += p2[(size_t)k * DH + jj];
        fc7s[jj] = fmaxf(s, 0.0f);
    }
    __syncthreads();

    float acc = 0.0f;
    if (o < 4) {
        for (int i = t; i < DH; i += 256)
            acc += fc7s[i] * Wloc[i * 4 + o];
    } else {
        const int a = o - 4;
        for (int i = t; i < DH; i += 256)
            acc += fc7s[i] * Wact[i * NACT + a];
    }
    __shared__ float sb[256];
    sb[t] = acc;
    __syncthreads();
    for (int st = 128; st > 0; st >>= 1) {
        if (t < st) sb[t] += sb[t + st];
        __syncthreads();
    }
    if (t == 0) {
        if (o < 4) g_loc[o] = sb[0] + bloc[o];
        else       out[8 + (o - 4)] = sb[0] + bact[o - 4];
    }
}

// ---------------------------------------------------------------------------
// Kernel 6: gaussian object selection + output assembly
// ---------------------------------------------------------------------------
__global__ void k_final(const int* __restrict__ imgshape, float* __restrict__ out)
{
    if (threadIdx.x != 0) return;
    const float img0 = (float)imgshape[0];
    const float img1 = (float)imgshape[1];

    const float hb0 = g_hbox[0], hb1 = g_hbox[1], hb2 = g_hbox[2], hb3 = g_hbox[3];
    const float hw_ = hb3 - hb1, hh_ = hb2 - hb0;
    const float h4x = 0.5f * hw_, h4y = 0.5f * hh_;
    const float hw = fmaxf(hw_, 1e-3f), hh = fmaxf(hh_, 1e-3f);

    const float mw = g_loc[3] - g_loc[1], mh = g_loc[2] - g_loc[0];
    const float mu0 = 0.5f * mw, mu1 = 0.5f * mh, mu2 = mw, mu3 = mh;

    float best = -1.0f;
    int   bl   = 0;
    for (int l = 0; l < 20; l++) {
        if (l == HUMAN_LBL) continue;
        const float b0 = g_kept[l][0], b1 = g_kept[l][1];
        const float b2 = g_kept[l][2], b3 = g_kept[l][3];
        const float cw_ = b3 - b1, ch_ = b2 - b0;
        const float cx = 0.5f * cw_, cy = 0.5f * ch_;
        const float cw = fmaxf(cw_, 1e-3f), ch = fmaxf(ch_, 1e-3f);
        const float d0 = (cx - h4x) / hw - mu0;
        const float d1 = (cy - h4y) / hh - mu1;
        const float d2 = logf(cw / hw) - mu2;
        const float d3 = logf(ch / hh) - mu3;
        const float gau = expf(-(d0*d0 + d1*d1 + d2*d2 + d3*d3) /
                               (2.0f * 0.3f * 0.3f));
        if (gau > best) { best = gau; bl = l; }
    }

    const float invy = img0 / (float)HFE;
    const float invx = img1 / (float)WFE;
    out[0] = hb0 * invy; out[1] = hb1 * invx;
    out[2] = hb2 * invy; out[3] = hb3 * invx;
    out[4] = g_kept[bl][0] * invy; out[5] = g_kept[bl][1] * invx;
    out[6] = g_kept[bl][2] * invy; out[7] = g_kept[bl][3] * invx;
    out[35] = (float)HFE / img0;
}

// ---------------------------------------------------------------------------
extern "C" void kernel_launch(void* const* d_in, const int* in_sizes, int n_in,
                              void* d_out, int out_size)
{
    const float* x        = (const float*)d_in[0];
    const float* pscores  = (const float*)d_in[1];
    const float* poff     = (const float*)d_in[2];
    const float* rois     = (const float*)d_in[3];
    const int*   imgshape = (const int*)  d_in[4];
    const float* W1       = (const float*)d_in[5];
    const float* b1       = (const float*)d_in[6];
    const float* W2       = (const float*)d_in[7];
    const float* b2       = (const float*)d_in[8];
    const float* Wloc     = (const float*)d_in[9];
    const float* bloc     = (const float*)d_in[10];
    const float* Wact     = (const float*)d_in[11];
    const float* bact     = (const float*)d_in[12];
    float* out = (float*)d_out;

    k_softprep<<<(R_ROIS + 255) / 256, 256>>>(pscores);
    k_select  <<<20, 256>>>(pscores, poff, rois, imgshape);
    k_roipool <<<(D1 + 255) / 256, 256>>>(x);
    k_gemv1   <<<SPLIT1 + PREF_BLKS, 256>>>((const float4*)W1, (const float4*)W2);
    k_gemv2   <<<dim3(4, SPLIT2), 256>>>((const float4*)W2, b1);
    k_heads   <<<31, 256>>>(Wloc, bloc, Wact, bact, b2, out);
    k_final   <<<1, 32>>>(imgshape, out);
}

// round 5
// speedup vs baseline: 1.2303x; 1.2303x over previous
#include <cuda_runtime.h>
#include <math.h>

// ---------------- problem constants -----------------------------------------
#define R_ROIS 2000
#define NOBJ   21
#define HFE    38
#define WFE    50
#define D1     25088        // 512*7*7
#define DH     4096
#define DH4    (DH/4)
#define NACT   27
#define HUMAN_LBL 14

#define SPLIT1 64
#define ROWS1  (D1/SPLIT1)  // 392 (= 8 channels of 49)
#define SPLIT2 32
#define ROWS2  (DH/SPLIT2)  // 128
#define PREF_BLKS 64
#define PREF_F4_PER_BLK ((DH*DH/4)/PREF_BLKS)   // 65536 float4 (1 MiB)
#define PREF_F4_PER_THR (PREF_F4_PER_BLK/256)   // 256 float4

// ---------------- device scratch --------------------------------------------
__device__ float  g_kept[20][4];
__device__ float  g_hbox[4];
__device__ float4 g_part1[SPLIT1 * DH4];
__device__ float  g_h1[DH];
__device__ float4 g_part2[SPLIT2 * DH4];
__device__ float  g_fc7[DH];
__device__ float  g_loc[4];
__device__ float  g_sink[PREF_BLKS * 256];   // prefetch DCE guard (never read)

// ---------------------------------------------------------------------------
// Kernel 1: fused softmax-normalizer + per-class argmax + box decode.
// 20 blocks (one per label), 256 threads. NMS_T=0 => greedy NMS keeps only
// the top-scoring box per class; argmax of prob == argmax of s[cls]-logZ.
// ---------------------------------------------------------------------------
__global__ void k_select(const float* __restrict__ scores,
                         const float* __restrict__ off,
                         const float* __restrict__ rois,
                         const int*   __restrict__ imgshape)
{
    const int l   = blockIdx.x;
    const int cls = l + 1;

    float best  = -1e30f;
    int   bestr = 0x7fffffff;
    for (int r = threadIdx.x; r < R_ROIS; r += blockDim.x) {
        const float* s = scores + r * NOBJ;
        float mx = s[0];
        #pragma unroll
        for (int j = 1; j < NOBJ; j++) mx = fmaxf(mx, s[j]);
        float sum = 0.0f;
        #pragma unroll
        for (int j = 0; j < NOBJ; j++) sum += expf(s[j] - mx);
        const float t = s[cls] - (mx + logf(sum));
        if (t > best) { best = t; bestr = r; }
    }

    __shared__ float sb[256];
    __shared__ int   si[256];
    sb[threadIdx.x] = best;
    si[threadIdx.x] = bestr;
    __syncthreads();
    for (int st = blockDim.x >> 1; st > 0; st >>= 1) {
        if (threadIdx.x < st) {
            float ob = sb[threadIdx.x + st];
            int   oi = si[threadIdx.x + st];
            if (ob > sb[threadIdx.x] ||
                (ob == sb[threadIdx.x] && oi < si[threadIdx.x])) {
                sb[threadIdx.x] = ob; si[threadIdx.x] = oi;
            }
        }
        __syncthreads();
    }

    if (threadIdx.x == 0) {
        const int r = si[0];
        const float img0 = (float)imgshape[0];
        const float img1 = (float)imgshape[1];
        const float sy = (float)HFE / img0;
        const float sx = (float)WFE / img1;
        const float y1 = rois[r * 4 + 0] * sy;
        const float x1 = rois[r * 4 + 1] * sx;
        const float y2 = rois[r * 4 + 2] * sy;
        const float x2 = rois[r * 4 + 3] * sx;
        const float dy = off[r * (NOBJ * 4) + cls * 4 + 0] * 0.1f;
        const float dx = off[r * (NOBJ * 4) + cls * 4 + 1] * 0.1f;
        const float dh = off[r * (NOBJ * 4) + cls * 4 + 2] * 0.2f;
        const float dw = off[r * (NOBJ * 4) + cls * 4 + 3] * 0.2f;
        const float h  = y2 - y1, w = x2 - x1;
        const float cy = y1 + 0.5f * h, cx = x1 + 0.5f * w;
        const float cy2 = dy * h + cy, cx2 = dx * w + cx;
        const float h2 = expf(dh) * h, w2 = expf(dw) * w;
        float by1 = fminf(fmaxf(cy2 - 0.5f * h2, 0.0f), (float)HFE);
        float bx1 = fminf(fmaxf(cx2 - 0.5f * w2, 0.0f), (float)WFE);
        float by2 = fminf(fmaxf(cy2 + 0.5f * h2, 0.0f), (float)HFE);
        float bx2 = fminf(fmaxf(cx2 + 0.5f * w2, 0.0f), (float)WFE);
        g_kept[l][0] = by1; g_kept[l][1] = bx1;
        g_kept[l][2] = by2; g_kept[l][3] = bx2;
        if (l == HUMAN_LBL) {
            g_hbox[0] = by1; g_hbox[1] = bx1;
            g_hbox[2] = by2; g_hbox[3] = bx2;
        }
    }
}

// ---------------------------------------------------------------------------
// roipool for one output element (device helper, identical math to reference)
// ---------------------------------------------------------------------------
__device__ __forceinline__ float roipool_one(const float* __restrict__ x, int idx)
{
    const int c  = idx / 49;
    const int ph = (idx % 49) / 7;
    const int pw = idx % 7;

    const float y1 = g_hbox[0], x1 = g_hbox[1], y2 = g_hbox[2], x2 = g_hbox[3];
    const int xmin = (int)rintf(x1 * 0.0625f);
    const int ymin = (int)rintf(y1 * 0.0625f);
    const int xmax = (int)rintf(x2 * 0.0625f);
    const int ymax = (int)rintf(y2 * 0.0625f);
    const float rw = (float)max(xmax - xmin + 1, 1);
    const float rh = (float)max(ymax - ymin + 1, 1);

    int hs = ymin + (int)floorf((float)ph * rh / 7.0f);
    int he = ymin + (int)ceilf((float)(ph + 1) * rh / 7.0f);
    int ws = xmin + (int)floorf((float)pw * rw / 7.0f);
    int we = xmin + (int)ceilf((float)(pw + 1) * rw / 7.0f);
    hs = min(max(hs, 0), HFE); he = min(max(he, 0), HFE);
    ws = min(max(ws, 0), WFE); we = min(max(we, 0), WFE);

    float m = -1e30f;
    for (int yy = hs; yy < he; yy++)
        for (int xx = ws; xx < we; xx++)
            m = fmaxf(m, x[c * (HFE * WFE) + yy * WFE + xx]);
    return (hs < he && ws < we) ? ((m <= -0.5e30f) ? 0.0f : m) : 0.0f;
}

// ---------------------------------------------------------------------------
// Kernel 2: GEMV1 split-K with fused roipool prologue + W2 L2-prefetch.
// grid (4, SPLIT1 + PREF_BLKS/4), 256 threads.
//  y <  SPLIT1 : compute block. Prologue computes its own 392 feat values
//                (8 channels; tiny pooling regions) straight into smem.
//  y >= SPLIT1 : stream 1 MiB of W2 into L2 (W1 reads use __ldcs evict-first).
// ---------------------------------------------------------------------------
__global__ void k_gemv1(const float4* __restrict__ W1,
                        const float4* __restrict__ W2,
                        const float*  __restrict__ x)
{
    const int t = threadIdx.x;

    if (blockIdx.y < SPLIT1) {
        const int i0 = blockIdx.y * ROWS1;

        __shared__ float sf[ROWS1];
        for (int f = t; f < ROWS1; f += 256)
            sf[f] = roipool_one(x, i0 + f);
        __syncthreads();

        const int j4 = blockIdx.x * 256 + t;
        float4 acc = make_float4(0.f, 0.f, 0.f, 0.f);
        const float4* __restrict__ w = W1 + (size_t)i0 * DH4 + j4;
        #pragma unroll 8
        for (int i = 0; i < ROWS1; i++) {
            const float4 v = __ldcs(&w[(size_t)i * DH4]);
            const float  s = sf[i];
            acc.x += s * v.x; acc.y += s * v.y;
            acc.z += s * v.z; acc.w += s * v.w;
        }
        g_part1[blockIdx.y * DH4 + j4] = acc;
    } else {
        const int pid = blockIdx.x * (PREF_BLKS / 4) + (blockIdx.y - SPLIT1);
        const size_t base = (size_t)pid * PREF_F4_PER_BLK + t;
        float acc = 0.0f;
        #pragma unroll 8
        for (int i = 0; i < PREF_F4_PER_THR; i++) {
            const float4 v = __ldg(&W2[base + (size_t)i * 256]);
            acc += v.x + v.y + v.z + v.w;
        }
        g_sink[pid * 256 + t] = acc;   // DCE guard, never read
    }
}

// ---------------------------------------------------------------------------
// Kernel 3: reduce1. 64 blocks x 256 threads (coalesced across j)
// ---------------------------------------------------------------------------
__global__ void k_reduce1(const float* __restrict__ b1)
{
    const int jl = threadIdx.x & 63;
    const int kq = threadIdx.x >> 6;
    const int j  = blockIdx.x * 64 + jl;
    const float* p1 = (const float*)g_part1;

    float s = 0.0f;
    #pragma unroll
    for (int k = 0; k < SPLIT1 / 4; k++)
        s += p1[(kq * (SPLIT1 / 4) + k) * DH + j];

    __shared__ float sm[4][64];
    sm[kq][jl] = s;
    __syncthreads();
    if (kq == 0) {
        float t = sm[0][jl] + sm[1][jl] + sm[2][jl] + sm[3][jl] + b1[j];
        g_h1[j] = fmaxf(t, 0.0f);
    }
}

// ---------------------------------------------------------------------------
// Kernel 4: GEMV2 split-K, float4 (W2 L2-resident from prefetch).
// grid (4, SPLIT2), 256 threads.
// ---------------------------------------------------------------------------
__global__ void k_gemv2(const float4* __restrict__ W2)
{
    const int j4 = blockIdx.x * 256 + threadIdx.x;
    const int i0 = blockIdx.y * ROWS2;

    __shared__ float sf[ROWS2];
    if (threadIdx.x < ROWS2) sf[threadIdx.x] = g_h1[i0 + threadIdx.x];
    __syncthreads();

    float4 acc = make_float4(0.f, 0.f, 0.f, 0.f);
    const float4* __restrict__ w = W2 + (size_t)i0 * DH4 + j4;
    #pragma unroll 8
    for (int i = 0; i < ROWS2; i++) {
        const float4 v = __ldg(&w[(size_t)i * DH4]);
        const float  s = sf[i];
        acc.x += s * v.x; acc.y += s * v.y;
        acc.z += s * v.z; acc.w += s * v.w;
    }
    g_part2[blockIdx.y * DH4 + j4] = acc;
}

// ---------------------------------------------------------------------------
// Kernel 5: reduce2. 64 blocks x 256 threads
// ---------------------------------------------------------------------------
__global__ void k_reduce2(const float* __restrict__ b2)
{
    const int jl = threadIdx.x & 63;
    const int kq = threadIdx.x >> 6;
    const int j  = blockIdx.x * 64 + jl;
    const float* p2 = (const float*)g_part2;

    float s = 0.0f;
    #pragma unroll
    for (int k = 0; k < SPLIT2 / 4; k++)
        s += p2[(kq * (SPLIT2 / 4) + k) * DH + j];

    __shared__ float sm[4][64];
    sm[kq][jl] = s;
    __syncthreads();
    if (kq == 0) {
        float t = sm[0][jl] + sm[1][jl] + sm[2][jl] + sm[3][jl] + b2[j];
        g_fc7[j] = fmaxf(t, 0.0f);
    }
}

// ---------------------------------------------------------------------------
// Kernel 6: heads. 31 blocks (4 loc + 27 act), 256 threads each.
// ---------------------------------------------------------------------------
__global__ void k_heads(const float* __restrict__ Wloc, const float* __restrict__ bloc,
                        const float* __restrict__ Wact, const float* __restrict__ bact,
                        float* __restrict__ out)
{
    const int o = blockIdx.x;
    float acc = 0.0f;
    if (o < 4) {
        for (int i = threadIdx.x; i < DH; i += 256)
            acc += g_fc7[i] * Wloc[i * 4 + o];
    } else {
        const int a = o - 4;
        for (int i = threadIdx.x; i < DH; i += 256)
            acc += g_fc7[i] * Wact[i * NACT + a];
    }
    __shared__ float sb[256];
    sb[threadIdx.x] = acc;
    __syncthreads();
    for (int st = 128; st > 0; st >>= 1) {
        if (threadIdx.x < st) sb[threadIdx.x] += sb[threadIdx.x + st];
        __syncthreads();
    }
    if (threadIdx.x == 0) {
        if (o < 4) g_loc[o] = sb[0] + bloc[o];
        else       out[8 + (o - 4)] = sb[0] + bact[o - 4];
    }
}

// ---------------------------------------------------------------------------
// Kernel 7: gaussian object selection + output assembly
// ---------------------------------------------------------------------------
__global__ void k_final(const int* __restrict__ imgshape, float* __restrict__ out)
{
    if (threadIdx.x != 0) return;
    const float img0 = (float)imgshape[0];
    const float img1 = (float)imgshape[1];

    const float hb0 = g_hbox[0], hb1 = g_hbox[1], hb2 = g_hbox[2], hb3 = g_hbox[3];
    const float hw_ = hb3 - hb1, hh_ = hb2 - hb0;
    const float h4x = 0.5f * hw_, h4y = 0.5f * hh_;
    const float hw = fmaxf(hw_, 1e-3f), hh = fmaxf(hh_, 1e-3f);

    const float mw = g_loc[3] - g_loc[1], mh = g_loc[2] - g_loc[0];
    const float mu0 = 0.5f * mw, mu1 = 0.5f * mh, mu2 = mw, mu3 = mh;

    float best = -1.0f;
    int   bl   = 0;
    for (int l = 0; l < 20; l++) {
        if (l == HUMAN_LBL) continue;
        const float b0 = g_kept[l][0], b1 = g_kept[l][1];
        const float b2 = g_kept[l][2], b3 = g_kept[l][3];
        const float cw_ = b3 - b1, ch_ = b2 - b0;
        const float cx = 0.5f * cw_, cy = 0.5f * ch_;
        const float cw = fmaxf(cw_, 1e-3f), ch = fmaxf(ch_, 1e-3f);
        const float d0 = (cx - h4x) / hw - mu0;
        const float d1 = (cy - h4y) / hh - mu1;
        const float d2 = logf(cw / hw) - mu2;
        const float d3 = logf(ch / hh) - mu3;
        const float gau = expf(-(d0*d0 + d1*d1 + d2*d2 + d3*d3) /
                               (2.0f * 0.3f * 0.3f));
        if (gau > best) { best = gau; bl = l; }
    }

    const float invy = img0 / (float)HFE;
    const float invx = img1 / (float)WFE;
    out[0] = hb0 * invy; out[1] = hb1 * invx;
    out[2] = hb2 * invy; out[3] = hb3 * invx;
    out[4] = g_kept[bl][0] * invy; out[5] = g_kept[bl][1] * invx;
    out[6] = g_kept[bl][2] * invy; out[7] = g_kept[bl][3] * invx;
    out[35] = (float)HFE / img0;
}

// ---------------------------------------------------------------------------
extern "C" void kernel_launch(void* const* d_in, const int* in_sizes, int n_in,
                              void* d_out, int out_size)
{
    const float* x        = (const float*)d_in[0];
    const float* pscores  = (const float*)d_in[1];
    const float* poff     = (const float*)d_in[2];
    const float* rois     = (const float*)d_in[3];
    const int*   imgshape = (const int*)  d_in[4];
    const float* W1       = (const float*)d_in[5];
    const float* b1       = (const float*)d_in[6];
    const float* W2       = (const float*)d_in[7];
    const float* b2       = (const float*)d_in[8];
    const float* Wloc     = (const float*)d_in[9];
    const float* bloc     = (const float*)d_in[10];
    const float* Wact     = (const float*)d_in[11];
    const float* bact     = (const float*)d_in[12];
    float* out = (float*)d_out;

    k_select <<<20, 256>>>(pscores, poff, rois, imgshape);
    k_gemv1  <<<dim3(4, SPLIT1 + PREF_BLKS / 4), 256>>>((const float4*)W1,
                                                        (const float4*)W2, x);
    k_reduce1<<<64, 256>>>(b1);
    k_gemv2  <<<dim3(4, SPLIT2), 256>>>((const float4*)W2);
    k_reduce2<<<64, 256>>>(b2);
    k_heads  <<<31, 256>>>(Wloc, bloc, Wact, bact, out);
    k_final  <<<1, 32>>>(imgshape, out);
}

// round 6
// speedup vs baseline: 1.3180x; 1.0713x over previous
#include <cuda_runtime.h>
#include <math.h>

// ---------------- problem constants -----------------------------------------
#define R_ROIS 2000
#define NOBJ   21
#define HFE    38
#define WFE    50
#define D1     25088        // 512*7*7
#define DH     4096
#define DH4    (DH/4)
#define NACT   27
#define HUMAN_LBL 14

#define SPLIT1 64
#define ROWS1  (D1/SPLIT1)  // 392
#define SPLIT2 128
#define ROWS2  (DH/SPLIT2)  // 32

// ---------------- device scratch --------------------------------------------
__device__ float  g_logZ[R_ROIS];
__device__ float  g_kept[20][4];
__device__ float  g_hbox[4];
__device__ float  g_feat[D1];
__device__ float4 g_part1[SPLIT1 * DH4];
__device__ float  g_h1[DH];
__device__ float4 g_part2[SPLIT2 * DH4];
__device__ float  g_fc7[DH];
__device__ float  g_loc[4];

// ---------------------------------------------------------------------------
// Kernel 0: per-roi softmax log-normalizer
// ---------------------------------------------------------------------------
__global__ void k_softprep(const float* __restrict__ scores)
{
    const int r = blockIdx.x * blockDim.x + threadIdx.x;
    if (r >= R_ROIS) return;
    const float* s = scores + r * NOBJ;
    float mx = s[0];
    #pragma unroll
    for (int j = 1; j < NOBJ; j++) mx = fmaxf(mx, s[j]);
    float sum = 0.0f;
    #pragma unroll
    for (int j = 0; j < NOBJ; j++) sum += expf(s[j] - mx);
    g_logZ[r] = mx + logf(sum);
}

// ---------------------------------------------------------------------------
// Kernel 1: per-class argmax (NMS_T=0 => top-1 per class) + box decode
// ---------------------------------------------------------------------------
__global__ void k_select(const float* __restrict__ scores,
                         const float* __restrict__ off,
                         const float* __restrict__ rois,
                         const int*   __restrict__ imgshape)
{
    const int l   = blockIdx.x;
    const int cls = l + 1;

    float best  = -1e30f;
    int   bestr = 0x7fffffff;
    for (int r = threadIdx.x; r < R_ROIS; r += blockDim.x) {
        const float t = scores[r * NOBJ + cls] - g_logZ[r];
        if (t > best) { best = t; bestr = r; }
    }

    __shared__ float sb[256];
    __shared__ int   si[256];
    sb[threadIdx.x] = best;
    si[threadIdx.x] = bestr;
    __syncthreads();
    for (int st = blockDim.x >> 1; st > 0; st >>= 1) {
        if (threadIdx.x < st) {
            float ob = sb[threadIdx.x + st];
            int   oi = si[threadIdx.x + st];
            if (ob > sb[threadIdx.x] ||
                (ob == sb[threadIdx.x] && oi < si[threadIdx.x])) {
                sb[threadIdx.x] = ob; si[threadIdx.x] = oi;
            }
        }
        __syncthreads();
    }

    if (threadIdx.x == 0) {
        const int r = si[0];
        const float img0 = (float)imgshape[0];
        const float img1 = (float)imgshape[1];
        const float sy = (float)HFE / img0;
        const float sx = (float)WFE / img1;
        const float y1 = rois[r * 4 + 0] * sy;
        const float x1 = rois[r * 4 + 1] * sx;
        const float y2 = rois[r * 4 + 2] * sy;
        const float x2 = rois[r * 4 + 3] * sx;
        const float dy = off[r * (NOBJ * 4) + cls * 4 + 0] * 0.1f;
        const float dx = off[r * (NOBJ * 4) + cls * 4 + 1] * 0.1f;
        const float dh = off[r * (NOBJ * 4) + cls * 4 + 2] * 0.2f;
        const float dw = off[r * (NOBJ * 4) + cls * 4 + 3] * 0.2f;
        const float h  = y2 - y1, w = x2 - x1;
        const float cy = y1 + 0.5f * h, cx = x1 + 0.5f * w;
        const float cy2 = dy * h + cy, cx2 = dx * w + cx;
        const float h2 = expf(dh) * h, w2 = expf(dw) * w;
        float by1 = fminf(fmaxf(cy2 - 0.5f * h2, 0.0f), (float)HFE);
        float bx1 = fminf(fmaxf(cx2 - 0.5f * w2, 0.0f), (float)WFE);
        float by2 = fminf(fmaxf(cy2 + 0.5f * h2, 0.0f), (float)HFE);
        float bx2 = fminf(fmaxf(cx2 + 0.5f * w2, 0.0f), (float)WFE);
        g_kept[l][0] = by1; g_kept[l][1] = bx1;
        g_kept[l][2] = by2; g_kept[l][3] = bx2;
        if (l == HUMAN_LBL) {
            g_hbox[0] = by1; g_hbox[1] = bx1;
            g_hbox[2] = by2; g_hbox[3] = bx2;
        }
    }
}

// ---------------------------------------------------------------------------
// Kernel 2: chainer-style RoIPooling2D on the human box
// ---------------------------------------------------------------------------
__global__ void k_roipool(const float* __restrict__ x)
{
    const int idx = blockIdx.x * blockDim.x + threadIdx.x;
    if (idx >= D1) return;
    const int c  = idx / 49;
    const int ph = (idx % 49) / 7;
    const int pw = idx % 7;

    const float y1 = g_hbox[0], x1 = g_hbox[1], y2 = g_hbox[2], x2 = g_hbox[3];
    const int xmin = (int)rintf(x1 * 0.0625f);
    const int ymin = (int)rintf(y1 * 0.0625f);
    const int xmax = (int)rintf(x2 * 0.0625f);
    const int ymax = (int)rintf(y2 * 0.0625f);
    const float rw = (float)max(xmax - xmin + 1, 1);
    const float rh = (float)max(ymax - ymin + 1, 1);

    int hs = ymin + (int)floorf((float)ph * rh / 7.0f);
    int he = ymin + (int)ceilf((float)(ph + 1) * rh / 7.0f);
    int ws = xmin + (int)floorf((float)pw * rw / 7.0f);
    int we = xmin + (int)ceilf((float)(pw + 1) * rw / 7.0f);
    hs = min(max(hs, 0), HFE); he = min(max(he, 0), HFE);
    ws = min(max(ws, 0), WFE); we = min(max(we, 0), WFE);

    float m = -1e30f;
    for (int yy = hs; yy < he; yy++)
        for (int xx = ws; xx < we; xx++)
            m = fmaxf(m, x[c * (HFE * WFE) + yy * WFE + xx]);
    g_feat[idx] = (hs < he && ws < we) ? ((m <= -0.5e30f) ? 0.0f : m) : 0.0f;
}

// ---------------------------------------------------------------------------
// Kernel 3: GEMV1 split-K, float4 streaming. grid (4, SPLIT1), block 256.
// ---------------------------------------------------------------------------
__global__ void k_gemv1(const float4* __restrict__ W1)
{
    const int t  = threadIdx.x;
    const int j4 = blockIdx.x * 256 + t;
    const int i0 = blockIdx.y * ROWS1;

    __shared__ float sf[ROWS1];
    for (int f = t; f < ROWS1; f += 256) sf[f] = g_feat[i0 + f];
    __syncthreads();

    float4 acc = make_float4(0.f, 0.f, 0.f, 0.f);
    const float4* __restrict__ w = W1 + (size_t)i0 * DH4 + j4;
    #pragma unroll 8
    for (int i = 0; i < ROWS1; i++) {
        const float4 v = __ldcs(&w[(size_t)i * DH4]);
        const float  s = sf[i];
        acc.x += s * v.x; acc.y += s * v.y;
        acc.z += s * v.z; acc.w += s * v.w;
    }
    g_part1[blockIdx.y * DH4 + j4] = acc;
}

// ---------------------------------------------------------------------------
// Kernel 4: reduce1. 64 blocks x 256 threads (coalesced across j)
// ---------------------------------------------------------------------------
__global__ void k_reduce1(const float* __restrict__ b1)
{
    const int jl = threadIdx.x & 63;
    const int kq = threadIdx.x >> 6;
    const int j  = blockIdx.x * 64 + jl;
    const float* p1 = (const float*)g_part1;

    float s = 0.0f;
    #pragma unroll
    for (int k = 0; k < SPLIT1 / 4; k++)
        s += p1[(kq * (SPLIT1 / 4) + k) * DH + j];

    __shared__ float sm[4][64];
    sm[kq][jl] = s;
    __syncthreads();
    if (kq == 0) {
        float t = sm[0][jl] + sm[1][jl] + sm[2][jl] + sm[3][jl] + b1[j];
        g_h1[j] = fmaxf(t, 0.0f);
    }
}

// ---------------------------------------------------------------------------
// Kernel 5: GEMV2 split-K, high parallelism. grid (4, SPLIT2=128), block 256.
// 512 blocks / 131k threads: latency-hiding by thread count, not depth.
// ---------------------------------------------------------------------------
__global__ void k_gemv2(const float4* __restrict__ W2)
{
    const int t  = threadIdx.x;
    const int j4 = blockIdx.x * 256 + t;
    const int i0 = blockIdx.y * ROWS2;

    __shared__ float sf[ROWS2];
    if (t < ROWS2) sf[t] = g_h1[i0 + t];
    __syncthreads();

    float4 acc = make_float4(0.f, 0.f, 0.f, 0.f);
    const float4* __restrict__ w = W2 + (size_t)i0 * DH4 + j4;
    #pragma unroll
    for (int i = 0; i < ROWS2; i++) {
        const float4 v = __ldcs(&w[(size_t)i * DH4]);
        const float  s = sf[i];
        acc.x += s * v.x; acc.y += s * v.y;
        acc.z += s * v.z; acc.w += s * v.w;
    }
    g_part2[blockIdx.y * DH4 + j4] = acc;
}

// ---------------------------------------------------------------------------
// Kernel 6: reduce2. 64 blocks x 256 threads, 128 partials per output.
// ---------------------------------------------------------------------------
__global__ void k_reduce2(const float* __restrict__ b2)
{
    const int jl = threadIdx.x & 63;
    const int kq = threadIdx.x >> 6;
    const int j  = blockIdx.x * 64 + jl;
    const float* p2 = (const float*)g_part2;

    float s = 0.0f;
    #pragma unroll 8
    for (int k = 0; k < SPLIT2 / 4; k++)
        s += p2[(size_t)(kq * (SPLIT2 / 4) + k) * DH + j];

    __shared__ float sm[4][64];
    sm[kq][jl] = s;
    __syncthreads();
    if (kq == 0) {
        float t = sm[0][jl] + sm[1][jl] + sm[2][jl] + sm[3][jl] + b2[j];
        g_fc7[j] = fmaxf(t, 0.0f);
    }
}

// ---------------------------------------------------------------------------
// Kernel 7: heads. 31 blocks (4 loc + 27 act), 256 threads each.
// ---------------------------------------------------------------------------
__global__ void k_heads(const float* __restrict__ Wloc, const float* __restrict__ bloc,
                        const float* __restrict__ Wact, const float* __restrict__ bact,
                        float* __restrict__ out)
{
    const int o = blockIdx.x;
    float acc = 0.0f;
    if (o < 4) {
        for (int i = threadIdx.x; i < DH; i += 256)
            acc += g_fc7[i] * Wloc[i * 4 + o];
    } else {
        const int a = o - 4;
        for (int i = threadIdx.x; i < DH; i += 256)
            acc += g_fc7[i] * Wact[i * NACT + a];
    }
    __shared__ float sb[256];
    sb[threadIdx.x] = acc;
    __syncthreads();
    for (int st = 128; st > 0; st >>= 1) {
        if (threadIdx.x < st) sb[threadIdx.x] += sb[threadIdx.x + st];
        __syncthreads();
    }
    if (threadIdx.x == 0) {
        if (o < 4) g_loc[o] = sb[0] + bloc[o];
        else       out[8 + (o - 4)] = sb[0] + bact[o - 4];
    }
}

// ---------------------------------------------------------------------------
// Kernel 8: gaussian object selection + output assembly
// ---------------------------------------------------------------------------
__global__ void k_final(const int* __restrict__ imgshape, float* __restrict__ out)
{
    if (threadIdx.x != 0) return;
    const float img0 = (float)imgshape[0];
    const float img1 = (float)imgshape[1];

    const float hb0 = g_hbox[0], hb1 = g_hbox[1], hb2 = g_hbox[2], hb3 = g_hbox[3];
    const float hw_ = hb3 - hb1, hh_ = hb2 - hb0;
    const float h4x = 0.5f * hw_, h4y = 0.5f * hh_;
    const float hw = fmaxf(hw_, 1e-3f), hh = fmaxf(hh_, 1e-3f);

    const float mw = g_loc[3] - g_loc[1], mh = g_loc[2] - g_loc[0];
    const float mu0 = 0.5f * mw, mu1 = 0.5f * mh, mu2 = mw, mu3 = mh;

    float best = -1.0f;
    int   bl   = 0;
    for (int l = 0; l < 20; l++) {
        if (l == HUMAN_LBL) continue;
        const float b0 = g_kept[l][0], b1 = g_kept[l][1];
        const float b2 = g_kept[l][2], b3 = g_kept[l][3];
        const float cw_ = b3 - b1, ch_ = b2 - b0;
        const float cx = 0.5f * cw_, cy = 0.5f * ch_;
        const float cw = fmaxf(cw_, 1e-3f), ch = fmaxf(ch_, 1e-3f);
        const float d0 = (cx - h4x) / hw - mu0;
        const float d1 = (cy - h4y) / hh - mu1;
        const float d2 = logf(cw / hw) - mu2;
        const float d3 = logf(ch / hh) - mu3;
        const float gau = expf(-(d0*d0 + d1*d1 + d2*d2 + d3*d3) /
                               (2.0f * 0.3f * 0.3f));
        if (gau > best) { best = gau; bl = l; }
    }

    const float invy = img0 / (float)HFE;
    const float invx = img1 / (float)WFE;
    out[0] = hb0 * invy; out[1] = hb1 * invx;
    out[2] = hb2 * invy; out[3] = hb3 * invx;
    out[4] = g_kept[bl][0] * invy; out[5] = g_kept[bl][1] * invx;
    out[6] = g_kept[bl][2] * invy; out[7] = g_kept[bl][3] * invx;
    out[35] = (float)HFE / img0;
}

// ---------------------------------------------------------------------------
extern "C" void kernel_launch(void* const* d_in, const int* in_sizes, int n_in,
                              void* d_out, int out_size)
{
    const float* x        = (const float*)d_in[0];
    const float* pscores  = (const float*)d_in[1];
    const float* poff     = (const float*)d_in[2];
    const float* rois     = (const float*)d_in[3];
    const int*   imgshape = (const int*)  d_in[4];
    const float* W1       = (const float*)d_in[5];
    const float* b1       = (const float*)d_in[6];
    const float* W2       = (const float*)d_in[7];
    const float* b2       = (const float*)d_in[8];
    const float* Wloc     = (const float*)d_in[9];
    const float* bloc     = (const float*)d_in[10];
    const float* Wact     = (const float*)d_in[11];
    const float* bact     = (const float*)d_in[12];
    float* out = (float*)d_out;

    k_softprep<<<(R_ROIS + 255) / 256, 256>>>(pscores);
    k_select  <<<20, 256>>>(pscores, poff, rois, imgshape);
    k_roipool <<<(D1 + 255) / 256, 256>>>(x);
    k_gemv1   <<<dim3(4, SPLIT1), 256>>>((const float4*)W1);
    k_reduce1 <<<64, 256>>>(b1);
    k_gemv2   <<<dim3(4, SPLIT2), 256>>>((const float4*)W2);
    k_reduce2 <<<64, 256>>>(b2);
    k_heads   <<<31, 256>>>(Wloc, bloc, Wact, bact, out);
    k_final   <<<1, 32>>>(imgshape, out);
}

// round 7
// speedup vs baseline: 1.4191x; 1.0767x over previous
#include <cuda_runtime.h>
#include <math.h>

// ---------------- problem constants -----------------------------------------
#define R_ROIS 2000
#define NOBJ   21
#define HFE    38
#define WFE    50
#define D1     25088        // 512*7*7
#define DH     4096
#define DH4    (DH/4)
#define NACT   27
#define HUMAN_LBL 14

#define SPLIT1 256
#define ROWS1  (D1/SPLIT1)  // 98
#define SPLIT2 128
#define ROWS2  (DH/SPLIT2)  // 32

// ---------------- device scratch --------------------------------------------
__device__ float  g_kept[20][4];
__device__ float  g_hbox[4];
__device__ float4 g_part1[SPLIT1 * DH4];
__device__ float  g_h1[DH];
__device__ float4 g_part2[SPLIT2 * DH4];
__device__ float  g_fc7[DH];
__device__ float  g_loc[4];

// ---------------------------------------------------------------------------
// Kernel 1: fused softmax + per-class argmax (NMS_T=0 => top-1/class) + decode
// 20 blocks, 256 threads. Each thread handles ~8 rois (21 exp each) — cheap.
// ---------------------------------------------------------------------------
__global__ void k_select(const float* __restrict__ scores,
                         const float* __restrict__ off,
                         const float* __restrict__ rois,
                         const int*   __restrict__ imgshape)
{
    const int l   = blockIdx.x;
    const int cls = l + 1;

    float best  = -1e30f;
    int   bestr = 0x7fffffff;
    for (int r = threadIdx.x; r < R_ROIS; r += blockDim.x) {
        const float* s = scores + r * NOBJ;
        float mx = s[0];
        #pragma unroll
        for (int j = 1; j < NOBJ; j++) mx = fmaxf(mx, s[j]);
        float sum = 0.0f;
        #pragma unroll
        for (int j = 0; j < NOBJ; j++) sum += expf(s[j] - mx);
        const float t = s[cls] - (mx + logf(sum));
        if (t > best) { best = t; bestr = r; }
    }

    __shared__ float sb[256];
    __shared__ int   si[256];
    sb[threadIdx.x] = best;
    si[threadIdx.x] = bestr;
    __syncthreads();
    for (int st = blockDim.x >> 1; st > 0; st >>= 1) {
        if (threadIdx.x < st) {
            float ob = sb[threadIdx.x + st];
            int   oi = si[threadIdx.x + st];
            if (ob > sb[threadIdx.x] ||
                (ob == sb[threadIdx.x] && oi < si[threadIdx.x])) {
                sb[threadIdx.x] = ob; si[threadIdx.x] = oi;
            }
        }
        __syncthreads();
    }

    if (threadIdx.x == 0) {
        const int r = si[0];
        const float img0 = (float)imgshape[0];
        const float img1 = (float)imgshape[1];
        const float sy = (float)HFE / img0;
        const float sx = (float)WFE / img1;
        const float y1 = rois[r * 4 + 0] * sy;
        const float x1 = rois[r * 4 + 1] * sx;
        const float y2 = rois[r * 4 + 2] * sy;
        const float x2 = rois[r * 4 + 3] * sx;
        const float dy = off[r * (NOBJ * 4) + cls * 4 + 0] * 0.1f;
        const float dx = off[r * (NOBJ * 4) + cls * 4 + 1] * 0.1f;
        const float dh = off[r * (NOBJ * 4) + cls * 4 + 2] * 0.2f;
        const float dw = off[r * (NOBJ * 4) + cls * 4 + 3] * 0.2f;
        const float h  = y2 - y1, w = x2 - x1;
        const float cy = y1 + 0.5f * h, cx = x1 + 0.5f * w;
        const float cy2 = dy * h + cy, cx2 = dx * w + cx;
        const float h2 = expf(dh) * h, w2 = expf(dw) * w;
        float by1 = fminf(fmaxf(cy2 - 0.5f * h2, 0.0f), (float)HFE);
        float bx1 = fminf(fmaxf(cx2 - 0.5f * w2, 0.0f), (float)WFE);
        float by2 = fminf(fmaxf(cy2 + 0.5f * h2, 0.0f), (float)HFE);
        float bx2 = fminf(fmaxf(cx2 + 0.5f * w2, 0.0f), (float)WFE);
        g_kept[l][0] = by1; g_kept[l][1] = bx1;
        g_kept[l][2] = by2; g_kept[l][3] = bx2;
        if (l == HUMAN_LBL) {
            g_hbox[0] = by1; g_hbox[1] = bx1;
            g_hbox[2] = by2; g_hbox[3] = bx2;
        }
    }
}

// ---------------------------------------------------------------------------
// roipool for one output element (same math as reference)
// ---------------------------------------------------------------------------
__device__ __forceinline__ float roipool_one(const float* __restrict__ x, int idx)
{
    const int c  = idx / 49;
    const int ph = (idx % 49) / 7;
    const int pw = idx % 7;

    const float y1 = g_hbox[0], x1 = g_hbox[1], y2 = g_hbox[2], x2 = g_hbox[3];
    const int xmin = (int)rintf(x1 * 0.0625f);
    const int ymin = (int)rintf(y1 * 0.0625f);
    const int xmax = (int)rintf(x2 * 0.0625f);
    const int ymax = (int)rintf(y2 * 0.0625f);
    const float rw = (float)max(xmax - xmin + 1, 1);
    const float rh = (float)max(ymax - ymin + 1, 1);

    int hs = ymin + (int)floorf((float)ph * rh / 7.0f);
    int he = ymin + (int)ceilf((float)(ph + 1) * rh / 7.0f);
    int ws = xmin + (int)floorf((float)pw * rw / 7.0f);
    int we = xmin + (int)ceilf((float)(pw + 1) * rw / 7.0f);
    hs = min(max(hs, 0), HFE); he = min(max(he, 0), HFE);
    ws = min(max(ws, 0), WFE); we = min(max(we, 0), WFE);

    float m = -1e30f;
    for (int yy = hs; yy < he; yy++)
        for (int xx = ws; xx < we; xx++)
            m = fmaxf(m, x[c * (HFE * WFE) + yy * WFE + xx]);
    return (hs < he && ws < we) ? ((m <= -0.5e30f) ? 0.0f : m) : 0.0f;
}

// ---------------------------------------------------------------------------
// Kernel 2: GEMV1 split-K with fused roipool prologue.
// grid (8, SPLIT1=256) = 2048 blocks, 128 threads — 13.8 blocks/SM, balanced.
// Each block: 98-row contiguous K-slab, 128 float4 columns, __ldcs streaming.
// ---------------------------------------------------------------------------
__global__ void k_gemv1(const float4* __restrict__ W1,
                        const float*  __restrict__ x)
{
    const int t  = threadIdx.x;
    const int i0 = blockIdx.y * ROWS1;

    __shared__ float sf[ROWS1];
    if (t < ROWS1) sf[t] = roipool_one(x, i0 + t);
    __syncthreads();

    const int j4 = blockIdx.x * 128 + t;
    float4 acc = make_float4(0.f, 0.f, 0.f, 0.f);
    const float4* __restrict__ w = W1 + (size_t)i0 * DH4 + j4;
    #pragma unroll 7
    for (int i = 0; i < ROWS1; i++) {
        const float4 v = __ldcs(&w[(size_t)i * DH4]);
        const float  s = sf[i];
        acc.x += s * v.x; acc.y += s * v.y;
        acc.z += s * v.z; acc.w += s * v.w;
    }
    g_part1[blockIdx.y * DH4 + j4] = acc;
}

// ---------------------------------------------------------------------------
// Kernel 3: reduce1. 64 blocks x 256 threads; 256 partials per output.
// ---------------------------------------------------------------------------
__global__ void k_reduce1(const float* __restrict__ b1)
{
    const int jl = threadIdx.x & 63;
    const int kq = threadIdx.x >> 6;
    const int j  = blockIdx.x * 64 + jl;
    const float* p1 = (const float*)g_part1;

    float s = 0.0f;
    #pragma unroll 8
    for (int k = 0; k < SPLIT1 / 4; k++)
        s += p1[(size_t)(kq * (SPLIT1 / 4) + k) * DH + j];

    __shared__ float sm[4][64];
    sm[kq][jl] = s;
    __syncthreads();
    if (kq == 0) {
        float t = sm[0][jl] + sm[1][jl] + sm[2][jl] + sm[3][jl] + b1[j];
        g_h1[j] = fmaxf(t, 0.0f);
    }
}

// ---------------------------------------------------------------------------
// Kernel 4: GEMV2 split-K. grid (8, SPLIT2=128) = 1024 blocks, 128 threads.
// ---------------------------------------------------------------------------
__global__ void k_gemv2(const float4* __restrict__ W2)
{
    const int t  = threadIdx.x;
    const int j4 = blockIdx.x * 128 + t;
    const int i0 = blockIdx.y * ROWS2;

    __shared__ float sf[ROWS2];
    if (t < ROWS2) sf[t] = g_h1[i0 + t];
    __syncthreads();

    float4 acc = make_float4(0.f, 0.f, 0.f, 0.f);
    const float4* __restrict__ w = W2 + (size_t)i0 * DH4 + j4;
    #pragma unroll
    for (int i = 0; i < ROWS2; i++) {
        const float4 v = __ldcs(&w[(size_t)i * DH4]);
        const float  s = sf[i];
        acc.x += s * v.x; acc.y += s * v.y;
        acc.z += s * v.z; acc.w += s * v.w;
    }
    g_part2[blockIdx.y * DH4 + j4] = acc;
}

// ---------------------------------------------------------------------------
// Kernel 5: reduce2. 64 blocks x 256 threads; 128 partials per output.
// ---------------------------------------------------------------------------
__global__ void k_reduce2(const float* __restrict__ b2)
{
    const int jl = threadIdx.x & 63;
    const int kq = threadIdx.x >> 6;
    const int j  = blockIdx.x * 64 + jl;
    const float* p2 = (const float*)g_part2;

    float s = 0.0f;
    #pragma unroll 8
    for (int k = 0; k < SPLIT2 / 4; k++)
        s += p2[(size_t)(kq * (SPLIT2 / 4) + k) * DH + j];

    __shared__ float sm[4][64];
    sm[kq][jl] = s;
    __syncthreads();
    if (kq == 0) {
        float t = sm[0][jl] + sm[1][jl] + sm[2][jl] + sm[3][jl] + b2[j];
        g_fc7[j] = fmaxf(t, 0.0f);
    }
}

// ---------------------------------------------------------------------------
// Kernel 6: heads. 31 blocks (4 loc + 27 act), 256 threads each.
// ---------------------------------------------------------------------------
__global__ void k_heads(const float* __restrict__ Wloc, const float* __restrict__ bloc,
                        const float* __restrict__ Wact, const float* __restrict__ bact,
                        float* __restrict__ out)
{
    const int o = blockIdx.x;
    float acc = 0.0f;
    if (o < 4) {
        for (int i = threadIdx.x; i < DH; i += 256)
            acc += g_fc7[i] * Wloc[i * 4 + o];
    } else {
        const int a = o - 4;
        for (int i = threadIdx.x; i < DH; i += 256)
            acc += g_fc7[i] * Wact[i * NACT + a];
    }
    __shared__ float sb[256];
    sb[threadIdx.x] = acc;
    __syncthreads();
    for (int st = 128; st > 0; st >>= 1) {
        if (threadIdx.x < st) sb[threadIdx.x] += sb[threadIdx.x + st];
        __syncthreads();
    }
    if (threadIdx.x == 0) {
        if (o < 4) g_loc[o] = sb[0] + bloc[o];
        else       out[8 + (o - 4)] = sb[0] + bact[o - 4];
    }
}

// ---------------------------------------------------------------------------
// Kernel 7: gaussian object selection + output assembly
// ---------------------------------------------------------------------------
__global__ void k_final(const int* __restrict__ imgshape, float* __restrict__ out)
{
    if (threadIdx.x != 0) return;
    const float img0 = (float)imgshape[0];
    const float img1 = (float)imgshape[1];

    const float hb0 = g_hbox[0], hb1 = g_hbox[1], hb2 = g_hbox[2], hb3 = g_hbox[3];
    const float hw_ = hb3 - hb1, hh_ = hb2 - hb0;
    const float h4x = 0.5f * hw_, h4y = 0.5f * hh_;
    const float hw = fmaxf(hw_, 1e-3f), hh = fmaxf(hh_, 1e-3f);

    const float mw = g_loc[3] - g_loc[1], mh = g_loc[2] - g_loc[0];
    const float mu0 = 0.5f * mw, mu1 = 0.5f * mh, mu2 = mw, mu3 = mh;

    float best = -1.0f;
    int   bl   = 0;
    for (int l = 0; l < 20; l++) {
        if (l == HUMAN_LBL) continue;
        const float b0 = g_kept[l][0], b1 = g_kept[l][1];
        const float b2 = g_kept[l][2], b3 = g_kept[l][3];
        const float cw_ = b3 - b1, ch_ = b2 - b0;
        const float cx = 0.5f * cw_, cy = 0.5f * ch_;
        const float cw = fmaxf(cw_, 1e-3f), ch = fmaxf(ch_, 1e-3f);
        const float d0 = (cx - h4x) / hw - mu0;
        const float d1 = (cy - h4y) / hh - mu1;
        const float d2 = logf(cw / hw) - mu2;
        const float d3 = logf(ch / hh) - mu3;
        const float gau = expf(-(d0*d0 + d1*d1 + d2*d2 + d3*d3) /
                               (2.0f * 0.3f * 0.3f));
        if (gau > best) { best = gau; bl = l; }
    }

    const float invy = img0 / (float)HFE;
    const float invx = img1 / (float)WFE;
    out[0] = hb0 * invy; out[1] = hb1 * invx;
    out[2] = hb2 * invy; out[3] = hb3 * invx;
    out[4] = g_kept[bl][0] * invy; out[5] = g_kept[bl][1] * invx;
    out[6] = g_kept[bl][2] * invy; out[7] = g_kept[bl][3] * invx;
    out[35] = (float)HFE / img0;
}

// ---------------------------------------------------------------------------
extern "C" void kernel_launch(void* const* d_in, const int* in_sizes, int n_in,
                              void* d_out, int out_size)
{
    const float* x        = (const float*)d_in[0];
    const float* pscores  = (const float*)d_in[1];
    const float* poff     = (const float*)d_in[2];
    const float* rois     = (const float*)d_in[3];
    const int*   imgshape = (const int*)  d_in[4];
    const float* W1       = (const float*)d_in[5];
    const float* b1       = (const float*)d_in[6];
    const float* W2       = (const float*)d_in[7];
    const float* b2       = (const float*)d_in[8];
    const float* Wloc     = (const float*)d_in[9];
    const float* bloc     = (const float*)d_in[10];
    const float* Wact     = (const float*)d_in[11];
    const float* bact     = (const float*)d_in[12];
    float* out = (float*)d_out;

    k_select <<<20, 256>>>(pscores, poff, rois, imgshape);
    k_gemv1  <<<dim3(8, SPLIT1), 128>>>((const float4*)W1, x);
    k_reduce1<<<64, 256>>>(b1);
    k_gemv2  <<<dim3(8, SPLIT2), 128>>>((const float4*)W2);
    k_reduce2<<<64, 256>>>(b2);
    k_heads  <<<31, 256>>>(Wloc, bloc, Wact, bact, out);
    k_final  <<<1, 32>>>(imgshape, out);
}

// round 8
// speedup vs baseline: 1.4319x; 1.0090x over previous
#include <cuda_runtime.h>
#include <math.h>

// ---------------- problem constants -----------------------------------------
#define R_ROIS 2000
#define NOBJ   21
#define HFE    38
#define WFE    50
#define D1     25088        // 512*7*7
#define DH     4096
#define DH4    (DH/4)
#define NACT   27
#define HUMAN_LBL 14

#define SPLIT1 256
#define ROWS1  (D1/SPLIT1)  // 98
#define SPLIT2 256
#define ROWS2  (DH/SPLIT2)  // 16

// ---------------- device scratch --------------------------------------------
__device__ float  g_kept[20][4];
__device__ float  g_hbox[4];
__device__ float4 g_part1[SPLIT1 * DH4];
__device__ float  g_h1[DH];
__device__ float4 g_part2[SPLIT2 * DH4];
__device__ float  g_fc7[DH];
__device__ float  g_loc[4];

// ---------------------------------------------------------------------------
// Kernel 1: fused softmax + per-class argmax (NMS_T=0 => top-1/class) + decode
// ---------------------------------------------------------------------------
__global__ void k_select(const float* __restrict__ scores,
                         const float* __restrict__ off,
                         const float* __restrict__ rois,
                         const int*   __restrict__ imgshape)
{
    const int l   = blockIdx.x;
    const int cls = l + 1;

    float best  = -1e30f;
    int   bestr = 0x7fffffff;
    for (int r = threadIdx.x; r < R_ROIS; r += blockDim.x) {
        const float* s = scores + r * NOBJ;
        float mx = s[0];
        #pragma unroll
        for (int j = 1; j < NOBJ; j++) mx = fmaxf(mx, s[j]);
        float sum = 0.0f;
        #pragma unroll
        for (int j = 0; j < NOBJ; j++) sum += expf(s[j] - mx);
        const float t = s[cls] - (mx + logf(sum));
        if (t > best) { best = t; bestr = r; }
    }

    __shared__ float sb[256];
    __shared__ int   si[256];
    sb[threadIdx.x] = best;
    si[threadIdx.x] = bestr;
    __syncthreads();
    for (int st = blockDim.x >> 1; st > 0; st >>= 1) {
        if (threadIdx.x < st) {
            float ob = sb[threadIdx.x + st];
            int   oi = si[threadIdx.x + st];
            if (ob > sb[threadIdx.x] ||
                (ob == sb[threadIdx.x] && oi < si[threadIdx.x])) {
                sb[threadIdx.x] = ob; si[threadIdx.x] = oi;
            }
        }
        __syncthreads();
    }

    if (threadIdx.x == 0) {
        const int r = si[0];
        const float img0 = (float)imgshape[0];
        const float img1 = (float)imgshape[1];
        const float sy = (float)HFE / img0;
        const float sx = (float)WFE / img1;
        const float y1 = rois[r * 4 + 0] * sy;
        const float x1 = rois[r * 4 + 1] * sx;
        const float y2 = rois[r * 4 + 2] * sy;
        const float x2 = rois[r * 4 + 3] * sx;
        const float dy = off[r * (NOBJ * 4) + cls * 4 + 0] * 0.1f;
        const float dx = off[r * (NOBJ * 4) + cls * 4 + 1] * 0.1f;
        const float dh = off[r * (NOBJ * 4) + cls * 4 + 2] * 0.2f;
        const float dw = off[r * (NOBJ * 4) + cls * 4 + 3] * 0.2f;
        const float h  = y2 - y1, w = x2 - x1;
        const float cy = y1 + 0.5f * h, cx = x1 + 0.5f * w;
        const float cy2 = dy * h + cy, cx2 = dx * w + cx;
        const float h2 = expf(dh) * h, w2 = expf(dw) * w;
        float by1 = fminf(fmaxf(cy2 - 0.5f * h2, 0.0f), (float)HFE);
        float bx1 = fminf(fmaxf(cx2 - 0.5f * w2, 0.0f), (float)WFE);
        float by2 = fminf(fmaxf(cy2 + 0.5f * h2, 0.0f), (float)HFE);
        float bx2 = fminf(fmaxf(cx2 + 0.5f * w2, 0.0f), (float)WFE);
        g_kept[l][0] = by1; g_kept[l][1] = bx1;
        g_kept[l][2] = by2; g_kept[l][3] = bx2;
        if (l == HUMAN_LBL) {
            g_hbox[0] = by1; g_hbox[1] = bx1;
            g_hbox[2] = by2; g_hbox[3] = bx2;
        }
    }
}

// ---------------------------------------------------------------------------
// roipool for one output element (same math as reference)
// ---------------------------------------------------------------------------
__device__ __forceinline__ float roipool_one(const float* __restrict__ x, int idx)
{
    const int c  = idx / 49;
    const int ph = (idx % 49) / 7;
    const int pw = idx % 7;

    const float y1 = g_hbox[0], x1 = g_hbox[1], y2 = g_hbox[2], x2 = g_hbox[3];
    const int xmin = (int)rintf(x1 * 0.0625f);
    const int ymin = (int)rintf(y1 * 0.0625f);
    const int xmax = (int)rintf(x2 * 0.0625f);
    const int ymax = (int)rintf(y2 * 0.0625f);
    const float rw = (float)max(xmax - xmin + 1, 1);
    const float rh = (float)max(ymax - ymin + 1, 1);

    int hs = ymin + (int)floorf((float)ph * rh / 7.0f);
    int he = ymin + (int)ceilf((float)(ph + 1) * rh / 7.0f);
    int ws = xmin + (int)floorf((float)pw * rw / 7.0f);
    int we = xmin + (int)ceilf((float)(pw + 1) * rw / 7.0f);
    hs = min(max(hs, 0), HFE); he = min(max(he, 0), HFE);
    ws = min(max(ws, 0), WFE); we = min(max(we, 0), WFE);

    float m = -1e30f;
    for (int yy = hs; yy < he; yy++)
        for (int xx = ws; xx < we; xx++)
            m = fmaxf(m, x[c * (HFE * WFE) + yy * WFE + xx]);
    return (hs < he && ws < we) ? ((m <= -0.5e30f) ? 0.0f : m) : 0.0f;
}

// ---------------------------------------------------------------------------
// Kernel 2: GEMV1 split-K with fused roipool prologue.
// grid (8, 256) = 2048 blocks, 128 threads — balanced 13.8 blocks/SM.
// ---------------------------------------------------------------------------
__global__ void k_gemv1(const float4* __restrict__ W1,
                        const float*  __restrict__ x)
{
    cudaGridDependencySynchronize();   // wait for k_select's g_hbox

    const int t  = threadIdx.x;
    const int i0 = blockIdx.y * ROWS1;

    __shared__ float sf[ROWS1];
    if (t < ROWS1) sf[t] = roipool_one(x, i0 + t);
    __syncthreads();

    const int j4 = blockIdx.x * 128 + t;
    float4 acc = make_float4(0.f, 0.f, 0.f, 0.f);
    const float4* __restrict__ w = W1 + (size_t)i0 * DH4 + j4;
    #pragma unroll 7
    for (int i = 0; i < ROWS1; i++) {
        const float4 v = __ldcs(&w[(size_t)i * DH4]);
        const float  s = sf[i];
        acc.x += s * v.x; acc.y += s * v.y;
        acc.z += s * v.z; acc.w += s * v.w;
    }
    g_part1[blockIdx.y * DH4 + j4] = acc;
}

// ---------------------------------------------------------------------------
// Kernel 3: reduce1. 64 blocks x 256 threads; 256 partials per output.
// ---------------------------------------------------------------------------
__global__ void k_reduce1(const float* __restrict__ b1)
{
    cudaGridDependencySynchronize();

    const int jl = threadIdx.x & 63;
    const int kq = threadIdx.x >> 6;
    const int j  = blockIdx.x * 64 + jl;
    const float* p1 = (const float*)g_part1;

    float s = 0.0f;
    #pragma unroll 8
    for (int k = 0; k < SPLIT1 / 4; k++)
        s += p1[(size_t)(kq * (SPLIT1 / 4) + k) * DH + j];

    __shared__ float sm[4][64];
    sm[kq][jl] = s;
    __syncthreads();
    if (kq == 0) {
        float t = sm[0][jl] + sm[1][jl] + sm[2][jl] + sm[3][jl] + b1[j];
        g_h1[j] = fmaxf(t, 0.0f);
    }
}

// ---------------------------------------------------------------------------
// Kernel 4: GEMV2 split-K. grid (8, 256) = 2048 blocks, 128 threads.
// ---------------------------------------------------------------------------
__global__ void k_gemv2(const float4* __restrict__ W2)
{
    cudaGridDependencySynchronize();

    const int t  = threadIdx.x;
    const int j4 = blockIdx.x * 128 + t;
    const int i0 = blockIdx.y * ROWS2;

    __shared__ float sf[ROWS2];
    if (t < ROWS2) sf[t] = g_h1[i0 + t];
    __syncthreads();

    float4 acc = make_float4(0.f, 0.f, 0.f, 0.f);
    const float4* __restrict__ w = W2 + (size_t)i0 * DH4 + j4;
    #pragma unroll
    for (int i = 0; i < ROWS2; i++) {
        const float4 v = __ldcs(&w[(size_t)i * DH4]);
        const float  s = sf[i];
        acc.x += s * v.x; acc.y += s * v.y;
        acc.z += s * v.z; acc.w += s * v.w;
    }
    g_part2[blockIdx.y * DH4 + j4] = acc;
}

// ---------------------------------------------------------------------------
// Kernel 5: reduce2. 64 blocks x 256 threads; 256 partials per output.
// ---------------------------------------------------------------------------
__global__ void k_reduce2(const float* __restrict__ b2)
{
    cudaGridDependencySynchronize();

    const int jl = threadIdx.x & 63;
    const int kq = threadIdx.x >> 6;
    const int j  = blockIdx.x * 64 + jl;
    const float* p2 = (const float*)g_part2;

    float s = 0.0f;
    #pragma unroll 8
    for (int k = 0; k < SPLIT2 / 4; k++)
        s += p2[(size_t)(kq * (SPLIT2 / 4) + k) * DH + j];

    __shared__ float sm[4][64];
    sm[kq][jl] = s;
    __syncthreads();
    if (kq == 0) {
        float t = sm[0][jl] + sm[1][jl] + sm[2][jl] + sm[3][jl] + b2[j];
        g_fc7[j] = fmaxf(t, 0.0f);
    }
}

// ---------------------------------------------------------------------------
// Kernel 6: heads. 31 blocks (4 loc + 27 act), 256 threads each.
// ---------------------------------------------------------------------------
__global__ void k_heads(const float* __restrict__ Wloc, const float* __restrict__ bloc,
                        const float* __restrict__ Wact, const float* __restrict__ bact,
                        float* __restrict__ out)
{
    cudaGridDependencySynchronize();

    const int o = blockIdx.x;
    float acc = 0.0f;
    if (o < 4) {
        for (int i = threadIdx.x; i < DH; i += 256)
            acc += g_fc7[i] * Wloc[i * 4 + o];
    } else {
        const int a = o - 4;
        for (int i = threadIdx.x; i < DH; i += 256)
            acc += g_fc7[i] * Wact[i * NACT + a];
    }
    __shared__ float sb[256];
    sb[threadIdx.x] = acc;
    __syncthreads();
    for (int st = 128; st > 0; st >>= 1) {
        if (threadIdx.x < st) sb[threadIdx.x] += sb[threadIdx.x + st];
        __syncthreads();
    }
    if (threadIdx.x == 0) {
        if (o < 4) g_loc[o] = sb[0] + bloc[o];
        else       out[8 + (o - 4)] = sb[0] + bact[o - 4];
    }
}

// ---------------------------------------------------------------------------
// Kernel 7: gaussian object selection + output assembly
// ---------------------------------------------------------------------------
__global__ void k_final(const int* __restrict__ imgshape, float* __restrict__ out)
{
    cudaGridDependencySynchronize();

    if (threadIdx.x != 0) return;
    const float img0 = (float)imgshape[0];
    const float img1 = (float)imgshape[1];

    const float hb0 = g_hbox[0], hb1 = g_hbox[1], hb2 = g_hbox[2], hb3 = g_hbox[3];
    const float hw_ = hb3 - hb1, hh_ = hb2 - hb0;
    const float h4x = 0.5f * hw_, h4y = 0.5f * hh_;
    const float hw = fmaxf(hw_, 1e-3f), hh = fmaxf(hh_, 1e-3f);

    const float mw = g_loc[3] - g_loc[1], mh = g_loc[2] - g_loc[0];
    const float mu0 = 0.5f * mw, mu1 = 0.5f * mh, mu2 = mw, mu3 = mh;

    float best = -1.0f;
    int   bl   = 0;
    for (int l = 0; l < 20; l++) {
        if (l == HUMAN_LBL) continue;
        const float b0 = g_kept[l][0], b1 = g_kept[l][1];
        const float b2 = g_kept[l][2], b3 = g_kept[l][3];
        const float cw_ = b3 - b1, ch_ = b2 - b0;
        const float cx = 0.5f * cw_, cy = 0.5f * ch_;
        const float cw = fmaxf(cw_, 1e-3f), ch = fmaxf(ch_, 1e-3f);
        const float d0 = (cx - h4x) / hw - mu0;
        const float d1 = (cy - h4y) / hh - mu1;
        const float d2 = logf(cw / hw) - mu2;
        const float d3 = logf(ch / hh) - mu3;
        const float gau = expf(-(d0*d0 + d1*d1 + d2*d2 + d3*d3) /
                               (2.0f * 0.3f * 0.3f));
        if (gau > best) { best = gau; bl = l; }
    }

    const float invy = img0 / (float)HFE;
    const float invx = img1 / (float)WFE;
    out[0] = hb0 * invy; out[1] = hb1 * invx;
    out[2] = hb2 * invy; out[3] = hb3 * invx;
    out[4] = g_kept[bl][0] * invy; out[5] = g_kept[bl][1] * invx;
    out[6] = g_kept[bl][2] * invy; out[7] = g_kept[bl][3] * invx;
    out[35] = (float)HFE / img0;
}

// ---------------------------------------------------------------------------
// PDL launch helper: enqueue with programmatic stream serialization so each
// kernel's launch overlaps its predecessor's tail (consumers gridsync).
// ---------------------------------------------------------------------------
static void launch_pdl(const void* func, dim3 grid, dim3 block, void** args)
{
    cudaLaunchConfig_t cfg = {};
    cfg.gridDim  = grid;
    cfg.blockDim = block;
    cudaLaunchAttribute attr[1];
    attr[0].id = cudaLaunchAttributeProgrammaticStreamSerialization;
    attr[0].val.programmaticStreamSerializationAllowed = 1;
    cfg.attrs = attr;
    cfg.numAttrs = 1;
    cudaLaunchKernelExC(&cfg, func, args);
}

// ---------------------------------------------------------------------------
extern "C" void kernel_launch(void* const* d_in, const int* in_sizes, int n_in,
                              void* d_out, int out_size)
{
    const float* x        = (const float*)d_in[0];
    const float* pscores  = (const float*)d_in[1];
    const float* poff     = (const float*)d_in[2];
    const float* rois     = (const float*)d_in[3];
    const int*   imgshape = (const int*)  d_in[4];
    const float* W1f      = (const float*)d_in[5];
    const float* b1       = (const float*)d_in[6];
    const float* W2f      = (const float*)d_in[7];
    const float* b2       = (const float*)d_in[8];
    const float* Wloc     = (const float*)d_in[9];
    const float* bloc     = (const float*)d_in[10];
    const float* Wact     = (const float*)d_in[11];
    const float* bact     = (const float*)d_in[12];
    float* out = (float*)d_out;
    const float4* W1 = (const float4*)W1f;
    const float4* W2 = (const float4*)W2f;

    {   // k_select
        void* a[] = {(void*)&pscores, (void*)&poff, (void*)&rois, (void*)&imgshape};
        launch_pdl((const void*)k_select, dim3(20), dim3(256), a);
    }
    {   // k_gemv1
        void* a[] = {(void*)&W1, (void*)&x};
        launch_pdl((const void*)k_gemv1, dim3(8, SPLIT1), dim3(128), a);
    }
    {   // k_reduce1
        void* a[] = {(void*)&b1};
        launch_pdl((const void*)k_reduce1, dim3(64), dim3(256), a);
    }
    {   // k_gemv2
        void* a[] = {(void*)&W2};
        launch_pdl((const void*)k_gemv2, dim3(8, SPLIT2), dim3(128), a);
    }
    {   // k_reduce2
        void* a[] = {(void*)&b2};
        launch_pdl((const void*)k_reduce2, dim3(64), dim3(256), a);
    }
    {   // k_heads
        void* a[] = {(void*)&Wloc, (void*)&bloc, (void*)&Wact, (void*)&bact, (void*)&out};
        launch_pdl((const void*)k_heads, dim3(31), dim3(256), a);
    }
    {   // k_final
        void* a[] = {(void*)&imgshape, (void*)&out};
        launch_pdl((const void*)k_final, dim3(1), dim3(32), a);
    }
}

// round 9
// speedup vs baseline: 1.5087x; 1.0536x over previous
#include <cuda_runtime.h>
#include <math.h>

// ---------------- problem constants -----------------------------------------
#define R_ROIS 2000
#define NOBJ   21
#define HFE    38
#define WFE    50
#define D1     25088        // 512*7*7
#define DH     4096
#define DH4    (DH/4)
#define NACT   27
#define HUMAN_LBL 14

#define SPLIT1 256
#define ROWS1  (D1/SPLIT1)  // 98
#define SPLIT2 256
#define ROWS2  (DH/SPLIT2)  // 16

// ---------------- device scratch --------------------------------------------
__device__ float  g_kept[20][4];
__device__ float  g_hbox[4];
__device__ float4 g_part1[SPLIT1 * DH4];
__device__ float  g_h1[DH];
__device__ float4 g_part2[SPLIT2 * DH4];
__device__ float  g_fc7[DH];
__device__ float  g_loc[4];

// ---------------------------------------------------------------------------
// Kernel 1: fused softmax + per-class argmax (NMS_T=0 => top-1/class) + decode
// ---------------------------------------------------------------------------
__global__ void k_select(const float* __restrict__ scores,
                         const float* __restrict__ off,
                         const float* __restrict__ rois,
                         const int*   __restrict__ imgshape)
{
    const int l   = blockIdx.x;
    const int cls = l + 1;

    float best  = -1e30f;
    int   bestr = 0x7fffffff;
    for (int r = threadIdx.x; r < R_ROIS; r += blockDim.x) {
        const float* s = scores + r * NOBJ;
        float mx = s[0];
        #pragma unroll
        for (int j = 1; j < NOBJ; j++) mx = fmaxf(mx, s[j]);
        float sum = 0.0f;
        #pragma unroll
        for (int j = 0; j < NOBJ; j++) sum += expf(s[j] - mx);
        const float t = s[cls] - (mx + logf(sum));
        if (t > best) { best = t; bestr = r; }
    }

    __shared__ float sb[256];
    __shared__ int   si[256];
    sb[threadIdx.x] = best;
    si[threadIdx.x] = bestr;
    __syncthreads();
    for (int st = blockDim.x >> 1; st > 0; st >>= 1) {
        if (threadIdx.x < st) {
            float ob = sb[threadIdx.x + st];
            int   oi = si[threadIdx.x + st];
            if (ob > sb[threadIdx.x] ||
                (ob == sb[threadIdx.x] && oi < si[threadIdx.x])) {
                sb[threadIdx.x] = ob; si[threadIdx.x] = oi;
            }
        }
        __syncthreads();
    }

    if (threadIdx.x == 0) {
        const int r = si[0];
        const float img0 = (float)imgshape[0];
        const float img1 = (float)imgshape[1];
        const float sy = (float)HFE / img0;
        const float sx = (float)WFE / img1;
        const float y1 = rois[r * 4 + 0] * sy;
        const float x1 = rois[r * 4 + 1] * sx;
        const float y2 = rois[r * 4 + 2] * sy;
        const float x2 = rois[r * 4 + 3] * sx;
        const float dy = off[r * (NOBJ * 4) + cls * 4 + 0] * 0.1f;
        const float dx = off[r * (NOBJ * 4) + cls * 4 + 1] * 0.1f;
        const float dh = off[r * (NOBJ * 4) + cls * 4 + 2] * 0.2f;
        const float dw = off[r * (NOBJ * 4) + cls * 4 + 3] * 0.2f;
        const float h  = y2 - y1, w = x2 - x1;
        const float cy = y1 + 0.5f * h, cx = x1 + 0.5f * w;
        const float cy2 = dy * h + cy, cx2 = dx * w + cx;
        const float h2 = expf(dh) * h, w2 = expf(dw) * w;
        float by1 = fminf(fmaxf(cy2 - 0.5f * h2, 0.0f), (float)HFE);
        float bx1 = fminf(fmaxf(cx2 - 0.5f * w2, 0.0f), (float)WFE);
        float by2 = fminf(fmaxf(cy2 + 0.5f * h2, 0.0f), (float)HFE);
        float bx2 = fminf(fmaxf(cx2 + 0.5f * w2, 0.0f), (float)WFE);
        g_kept[l][0] = by1; g_kept[l][1] = bx1;
        g_kept[l][2] = by2; g_kept[l][3] = bx2;
        if (l == HUMAN_LBL) {
            g_hbox[0] = by1; g_hbox[1] = bx1;
            g_hbox[2] = by2; g_hbox[3] = bx2;
        }
    }
}

// ---------------------------------------------------------------------------
// roipool for one output element (same math as reference)
// ---------------------------------------------------------------------------
__device__ __forceinline__ float roipool_one(const float* __restrict__ x, int idx)
{
    const int c  = idx / 49;
    const int ph = (idx % 49) / 7;
    const int pw = idx % 7;

    const float y1 = g_hbox[0], x1 = g_hbox[1], y2 = g_hbox[2], x2 = g_hbox[3];
    const int xmin = (int)rintf(x1 * 0.0625f);
    const int ymin = (int)rintf(y1 * 0.0625f);
    const int xmax = (int)rintf(x2 * 0.0625f);
    const int ymax = (int)rintf(y2 * 0.0625f);
    const float rw = (float)max(xmax - xmin + 1, 1);
    const float rh = (float)max(ymax - ymin + 1, 1);

    int hs = ymin + (int)floorf((float)ph * rh / 7.0f);
    int he = ymin + (int)ceilf((float)(ph + 1) * rh / 7.0f);
    int ws = xmin + (int)floorf((float)pw * rw / 7.0f);
    int we = xmin + (int)ceilf((float)(pw + 1) * rw / 7.0f);
    hs = min(max(hs, 0), HFE); he = min(max(he, 0), HFE);
    ws = min(max(ws, 0), WFE); we = min(max(we, 0), WFE);

    float m = -1e30f;
    for (int yy = hs; yy < he; yy++)
        for (int xx = ws; xx < we; xx++)
            m = fmaxf(m, x[c * (HFE * WFE) + yy * WFE + xx]);
    return (hs < he && ws < we) ? ((m <= -0.5e30f) ? 0.0f : m) : 0.0f;
}

// ---------------------------------------------------------------------------
// Kernel 2: GEMV1 split-K with fused roipool prologue.
// grid (8, 256) = 2048 blocks, 128 threads — balanced 13.8 blocks/SM.
// ---------------------------------------------------------------------------
__global__ void k_gemv1(const float4* __restrict__ W1,
                        const float*  __restrict__ x)
{
    cudaGridDependencySynchronize();   // wait for k_select's g_hbox

    const int t  = threadIdx.x;
    const int i0 = blockIdx.y * ROWS1;

    __shared__ float sf[ROWS1];
    if (t < ROWS1) sf[t] = roipool_one(x, i0 + t);
    __syncthreads();

    const int j4 = blockIdx.x * 128 + t;
    float4 acc = make_float4(0.f, 0.f, 0.f, 0.f);
    const float4* __restrict__ w = W1 + (size_t)i0 * DH4 + j4;
    #pragma unroll 7
    for (int i = 0; i < ROWS1; i++) {
        const float4 v = __ldcs(&w[(size_t)i * DH4]);
        const float  s = sf[i];
        acc.x += s * v.x; acc.y += s * v.y;
        acc.z += s * v.z; acc.w += s * v.w;
    }
    g_part1[blockIdx.y * DH4 + j4] = acc;
}

// ---------------------------------------------------------------------------
// Kernel 3: reduce1. 64 blocks x 256 threads; 256 partials per output.
// ---------------------------------------------------------------------------
__global__ void k_reduce1(const float* __restrict__ b1)
{
    cudaGridDependencySynchronize();

    const int jl = threadIdx.x & 63;
    const int kq = threadIdx.x >> 6;
    const int j  = blockIdx.x * 64 + jl;
    const float* p1 = (const float*)g_part1;

    float s = 0.0f;
    #pragma unroll 8
    for (int k = 0; k < SPLIT1 / 4; k++)
        s += p1[(size_t)(kq * (SPLIT1 / 4) + k) * DH + j];

    __shared__ float sm[4][64];
    sm[kq][jl] = s;
    __syncthreads();
    if (kq == 0) {
        float t = sm[0][jl] + sm[1][jl] + sm[2][jl] + sm[3][jl] + b1[j];
        g_h1[j] = fmaxf(t, 0.0f);
    }
}

// ---------------------------------------------------------------------------
// Kernel 4: GEMV2 split-K with ReLU zero-skip.
// grid (8, 256) = 2048 blocks, 128 threads. ~50% of h1 is exactly 0 (ReLU on
// zero-mean data) — skipping those rows is exact math and halves W2 traffic.
// Skip test is block-uniform (smem value) => no divergence; row granularity
// (2KB bursts) keeps DRAM efficiency.
// ---------------------------------------------------------------------------
__global__ void k_gemv2(const float4* __restrict__ W2)
{
    cudaGridDependencySynchronize();

    const int t  = threadIdx.x;
    const int j4 = blockIdx.x * 128 + t;
    const int i0 = blockIdx.y * ROWS2;

    __shared__ float sf[ROWS2];
    if (t < ROWS2) sf[t] = g_h1[i0 + t];
    __syncthreads();

    float4 acc = make_float4(0.f, 0.f, 0.f, 0.f);
    const float4* __restrict__ w = W2 + (size_t)i0 * DH4 + j4;
    #pragma unroll
    for (int i = 0; i < ROWS2; i++) {
        const float s = sf[i];
        if (s != 0.0f) {                       // block-uniform branch
            const float4 v = __ldcs(&w[(size_t)i * DH4]);
            acc.x += s * v.x; acc.y += s * v.y;
            acc.z += s * v.z; acc.w += s * v.w;
        }
    }
    g_part2[blockIdx.y * DH4 + j4] = acc;
}

// ---------------------------------------------------------------------------
// Kernel 5: reduce2. 64 blocks x 256 threads; 256 partials per output.
// ---------------------------------------------------------------------------
__global__ void k_reduce2(const float* __restrict__ b2)
{
    cudaGridDependencySynchronize();

    const int jl = threadIdx.x & 63;
    const int kq = threadIdx.x >> 6;
    const int j  = blockIdx.x * 64 + jl;
    const float* p2 = (const float*)g_part2;

    float s = 0.0f;
    #pragma unroll 8
    for (int k = 0; k < SPLIT2 / 4; k++)
        s += p2[(size_t)(kq * (SPLIT2 / 4) + k) * DH + j];

    __shared__ float sm[4][64];
    sm[kq][jl] = s;
    __syncthreads();
    if (kq == 0) {
        float t = sm[0][jl] + sm[1][jl] + sm[2][jl] + sm[3][jl] + b2[j];
        g_fc7[j] = fmaxf(t, 0.0f);
    }
}

// ---------------------------------------------------------------------------
// Kernel 6: heads. 31 blocks (4 loc + 27 act), 256 threads each.
// ---------------------------------------------------------------------------
__global__ void k_heads(const float* __restrict__ Wloc, const float* __restrict__ bloc,
                        const float* __restrict__ Wact, const float* __restrict__ bact,
                        float* __restrict__ out)
{
    cudaGridDependencySynchronize();

    const int o = blockIdx.x;
    float acc = 0.0f;
    if (o < 4) {
        for (int i = threadIdx.x; i < DH; i += 256)
            acc += g_fc7[i] * Wloc[i * 4 + o];
    } else {
        const int a = o - 4;
        for (int i = threadIdx.x; i < DH; i += 256)
            acc += g_fc7[i] * Wact[i * NACT + a];
    }
    __shared__ float sb[256];
    sb[threadIdx.x] = acc;
    __syncthreads();
    for (int st = 128; st > 0; st >>= 1) {
        if (threadIdx.x < st) sb[threadIdx.x] += sb[threadIdx.x + st];
        __syncthreads();
    }
    if (threadIdx.x == 0) {
        if (o < 4) g_loc[o] = sb[0] + bloc[o];
        else       out[8 + (o - 4)] = sb[0] + bact[o - 4];
    }
}

// ---------------------------------------------------------------------------
// Kernel 7: gaussian object selection + output assembly
// ---------------------------------------------------------------------------
__global__ void k_final(const int* __restrict__ imgshape, float* __restrict__ out)
{
    cudaGridDependencySynchronize();

    if (threadIdx.x != 0) return;
    const float img0 = (float)imgshape[0];
    const float img1 = (float)imgshape[1];

    const float hb0 = g_hbox[0], hb1 = g_hbox[1], hb2 = g_hbox[2], hb3 = g_hbox[3];
    const float hw_ = hb3 - hb1, hh_ = hb2 - hb0;
    const float h4x = 0.5f * hw_, h4y = 0.5f * hh_;
    const float hw = fmaxf(hw_, 1e-3f), hh = fmaxf(hh_, 1e-3f);

    const float mw = g_loc[3] - g_loc[1], mh = g_loc[2] - g_loc[0];
    const float mu0 = 0.5f * mw, mu1 = 0.5f * mh, mu2 = mw, mu3 = mh;

    float best = -1.0f;
    int   bl   = 0;
    for (int l = 0; l < 20; l++) {
        if (l == HUMAN_LBL) continue;
        const float b0 = g_kept[l][0], b1 = g_kept[l][1];
        const float b2 = g_kept[l][2], b3 = g_kept[l][3];
        const float cw_ = b3 - b1, ch_ = b2 - b0;
        const float cx = 0.5f * cw_, cy = 0.5f * ch_;
        const float cw = fmaxf(cw_, 1e-3f), ch = fmaxf(ch_, 1e-3f);
        const float d0 = (cx - h4x) / hw - mu0;
        const float d1 = (cy - h4y) / hh - mu1;
        const float d2 = logf(cw / hw) - mu2;
        const float d3 = logf(ch / hh) - mu3;
        const float gau = expf(-(d0*d0 + d1*d1 + d2*d2 + d3*d3) /
                               (2.0f * 0.3f * 0.3f));
        if (gau > best) { best = gau; bl = l; }
    }

    const float invy = img0 / (float)HFE;
    const float invx = img1 / (float)WFE;
    out[0] = hb0 * invy; out[1] = hb1 * invx;
    out[2] = hb2 * invy; out[3] = hb3 * invx;
    out[4] = g_kept[bl][0] * invy; out[5] = g_kept[bl][1] * invx;
    out[6] = g_kept[bl][2] * invy; out[7] = g_kept[bl][3] * invx;
    out[35] = (float)HFE / img0;
}

// ---------------------------------------------------------------------------
// PDL launch helper
// ---------------------------------------------------------------------------
static void launch_pdl(const void* func, dim3 grid, dim3 block, void** args)
{
    cudaLaunchConfig_t cfg = {};
    cfg.gridDim  = grid;
    cfg.blockDim = block;
    cudaLaunchAttribute attr[1];
    attr[0].id = cudaLaunchAttributeProgrammaticStreamSerialization;
    attr[0].val.programmaticStreamSerializationAllowed = 1;
    cfg.attrs = attr;
    cfg.numAttrs = 1;
    cudaLaunchKernelExC(&cfg, func, args);
}

// ---------------------------------------------------------------------------
extern "C" void kernel_launch(void* const* d_in, const int* in_sizes, int n_in,
                              void* d_out, int out_size)
{
    const float* x        = (const float*)d_in[0];
    const float* pscores  = (const float*)d_in[1];
    const float* poff     = (const float*)d_in[2];
    const float* rois     = (const float*)d_in[3];
    const int*   imgshape = (const int*)  d_in[4];
    const float* W1f      = (const float*)d_in[5];
    const float* b1       = (const float*)d_in[6];
    const float* W2f      = (const float*)d_in[7];
    const float* b2       = (const float*)d_in[8];
    const float* Wloc     = (const float*)d_in[9];
    const float* bloc     = (const float*)d_in[10];
    const float* Wact     = (const float*)d_in[11];
    const float* bact     = (const float*)d_in[12];
    float* out = (float*)d_out;
    const float4* W1 = (const float4*)W1f;
    const float4* W2 = (const float4*)W2f;

    {   void* a[] = {(void*)&pscores, (void*)&poff, (void*)&rois, (void*)&imgshape};
        launch_pdl((const void*)k_select, dim3(20), dim3(256), a); }
    {   void* a[] = {(void*)&W1, (void*)&x};
        launch_pdl((const void*)k_gemv1, dim3(8, SPLIT1), dim3(128), a); }
    {   void* a[] = {(void*)&b1};
        launch_pdl((const void*)k_reduce1, dim3(64), dim3(256), a); }
    {   void* a[] = {(void*)&W2};
        launch_pdl((const void*)k_gemv2, dim3(8, SPLIT2), dim3(128), a); }
    {   void* a[] = {(void*)&b2};
        launch_pdl((const void*)k_reduce2, dim3(64), dim3(256), a); }
    {   void* a[] = {(void*)&Wloc, (void*)&bloc, (void*)&Wact, (void*)&bact, (void*)&out};
        launch_pdl((const void*)k_heads, dim3(31), dim3(256), a); }
    {   void* a[] = {(void*)&imgshape, (void*)&out};
        launch_pdl((const void*)k_final, dim3(1), dim3(32), a); }
}

// round 10
// speedup vs baseline: 1.6061x; 1.0645x over previous
#include <cuda_runtime.h>
#include <math.h>

// ---------------- problem constants -----------------------------------------
#define R_ROIS 2000
#define NOBJ   21
#define HFE    38
#define WFE    50
#define D1     25088        // 512*7*7
#define DH     4096
#define DH4    (DH/4)
#define NACT   27
#define HUMAN_LBL 14

#define SPLIT1 256
#define ROWS1  (D1/SPLIT1)  // 98
#define SPLIT2 256
#define ROWS2  (DH/SPLIT2)  // 16
#define SELC   8            // roi chunks in select stage A

// ---------------- device scratch --------------------------------------------
__device__ float  g_selv[20][SELC];
__device__ int    g_seli[20][SELC];
__device__ float  g_kept[20][4];
__device__ float  g_hbox[4];
__device__ float4 g_part1[SPLIT1 * DH4];
__device__ float  g_h1[DH];
__device__ float4 g_part2[SPLIT2 * DH4];
__device__ float  g_hp[64 * 31];     // per-block head partials
__device__ float  g_sink[16];        // prefetch DCE guard

// ---------------------------------------------------------------------------
// Kernel 1a: select stage A — per-(label, roi-chunk) partial argmax of
// softmax prob (NMS_T=0 => greedy NMS keeps only the top-1 box per class;
// argmax of prob == argmax of s[cls] - logsumexp(s)).
// grid (SELC, 21): by<20 = labels; by==20 = Wloc/Wact L2 prefetch row.
// ---------------------------------------------------------------------------
__global__ void k_selA(const float* __restrict__ scores,
                       const float* __restrict__ Wloc,
                       const float* __restrict__ Wact)
{
    cudaGridDependencySynchronize();
    const int t = threadIdx.x;

    if (blockIdx.y == 20) {
        // prefetch heads weights into L2 (evict-normal): 31744 float4 total
        const float4* wl = (const float4*)Wloc;   // 4096 float4
        const float4* wa = (const float4*)Wact;   // 27648 float4
        float acc = 0.0f;
        for (int i = blockIdx.x * 256 + t; i < 4096;  i += SELC * 256) {
            const float4 v = __ldg(&wl[i]); acc += v.x + v.y + v.z + v.w;
        }
        for (int i = blockIdx.x * 256 + t; i < 27648; i += SELC * 256) {
            const float4 v = __ldg(&wa[i]); acc += v.x + v.y + v.z + v.w;
        }
        if (acc == 1e30f) g_sink[blockIdx.x] = acc;  // never true; defeats DCE
        return;
    }

    const int l   = blockIdx.y;
    const int cls = l + 1;
    const int r   = blockIdx.x * 256 + t;

    float best  = -1e30f;
    int   bestr = 0x7fffffff;
    if (r < R_ROIS) {
        const float* s = scores + r * NOBJ;
        float mx = s[0];
        #pragma unroll
        for (int j = 1; j < NOBJ; j++) mx = fmaxf(mx, s[j]);
        float sum = 0.0f;
        #pragma unroll
        for (int j = 0; j < NOBJ; j++) sum += expf(s[j] - mx);
        best  = s[cls] - (mx + logf(sum));
        bestr = r;
    }

    __shared__ float sb[256];
    __shared__ int   si[256];
    sb[t] = best; si[t] = bestr;
    __syncthreads();
    for (int st = 128; st > 0; st >>= 1) {
        if (t < st) {
            float ob = sb[t + st]; int oi = si[t + st];
            if (ob > sb[t] || (ob == sb[t] && oi < si[t])) { sb[t] = ob; si[t] = oi; }
        }
        __syncthreads();
    }
    if (t == 0) { g_selv[l][blockIdx.x] = sb[0]; g_seli[l][blockIdx.x] = si[0]; }
}

// ---------------------------------------------------------------------------
// Kernel 1b: select stage B — final argmax across chunks + box decode.
// 1 block, 32 threads; thread l handles label l.
// ---------------------------------------------------------------------------
__global__ void k_selB(const float* __restrict__ off,
                       const float* __restrict__ rois,
                       const int*   __restrict__ imgshape)
{
    cudaGridDependencySynchronize();
    const int l = threadIdx.x;
    if (l >= 20) return;
    const int cls = l + 1;

    float best = -1e30f;
    int   r    = 0x7fffffff;
    #pragma unroll
    for (int c = 0; c < SELC; c++) {        // ascending chunks + strict > ==
        const float v = g_selv[l][c];       // global first-max semantics
        if (v > best) { best = v; r = g_seli[l][c]; }
    }

    const float img0 = (float)imgshape[0];
    const float img1 = (float)imgshape[1];
    const float sy = (float)HFE / img0;
    const float sx = (float)WFE / img1;
    const float y1 = rois[r * 4 + 0] * sy;
    const float x1 = rois[r * 4 + 1] * sx;
    const float y2 = rois[r * 4 + 2] * sy;
    const float x2 = rois[r * 4 + 3] * sx;
    const float dy = off[r * (NOBJ * 4) + cls * 4 + 0] * 0.1f;
    const float dx = off[r * (NOBJ * 4) + cls * 4 + 1] * 0.1f;
    const float dh = off[r * (NOBJ * 4) + cls * 4 + 2] * 0.2f;
    const float dw = off[r * (NOBJ * 4) + cls * 4 + 3] * 0.2f;
    const float h  = y2 - y1, w = x2 - x1;
    const float cy = y1 + 0.5f * h, cx = x1 + 0.5f * w;
    const float cy2 = dy * h + cy, cx2 = dx * w + cx;
    const float h2 = expf(dh) * h, w2 = expf(dw) * w;
    float by1 = fminf(fmaxf(cy2 - 0.5f * h2, 0.0f), (float)HFE);
    float bx1 = fminf(fmaxf(cx2 - 0.5f * w2, 0.0f), (float)WFE);
    float by2 = fminf(fmaxf(cy2 + 0.5f * h2, 0.0f), (float)HFE);
    float bx2 = fminf(fmaxf(cx2 + 0.5f * w2, 0.0f), (float)WFE);
    g_kept[l][0] = by1; g_kept[l][1] = bx1;
    g_kept[l][2] = by2; g_kept[l][3] = bx2;
    if (l == HUMAN_LBL) {
        g_hbox[0] = by1; g_hbox[1] = bx1;
        g_hbox[2] = by2; g_hbox[3] = bx2;
    }
}

// ---------------------------------------------------------------------------
// roipool for one output element (same math as reference)
// ---------------------------------------------------------------------------
__device__ __forceinline__ float roipool_one(const float* __restrict__ x, int idx)
{
    const int c  = idx / 49;
    const int ph = (idx % 49) / 7;
    const int pw = idx % 7;

    const float y1 = g_hbox[0], x1 = g_hbox[1], y2 = g_hbox[2], x2 = g_hbox[3];
    const int xmin = (int)rintf(x1 * 0.0625f);
    const int ymin = (int)rintf(y1 * 0.0625f);
    const int xmax = (int)rintf(x2 * 0.0625f);
    const int ymax = (int)rintf(y2 * 0.0625f);
    const float rw = (float)max(xmax - xmin + 1, 1);
    const float rh = (float)max(ymax - ymin + 1, 1);

    int hs = ymin + (int)floorf((float)ph * rh / 7.0f);
    int he = ymin + (int)ceilf((float)(ph + 1) * rh / 7.0f);
    int ws = xmin + (int)floorf((float)pw * rw / 7.0f);
    int we = xmin + (int)ceilf((float)(pw + 1) * rw / 7.0f);
    hs = min(max(hs, 0), HFE); he = min(max(he, 0), HFE);
    ws = min(max(ws, 0), WFE); we = min(max(we, 0), WFE);

    float m = -1e30f;
    for (int yy = hs; yy < he; yy++)
        for (int xx = ws; xx < we; xx++)
            m = fmaxf(m, x[c * (HFE * WFE) + yy * WFE + xx]);
    return (hs < he && ws < we) ? ((m <= -0.5e30f) ? 0.0f : m) : 0.0f;
}

// ---------------------------------------------------------------------------
// Kernel 2: GEMV1 split-K with fused roipool prologue.
// grid (8, 256) = 2048 blocks, 128 threads. W1 streamed evict-first.
// ---------------------------------------------------------------------------
__global__ void k_gemv1(const float4* __restrict__ W1,
                        const float*  __restrict__ x)
{
    cudaGridDependencySynchronize();

    const int t  = threadIdx.x;
    const int i0 = blockIdx.y * ROWS1;

    __shared__ float sf[ROWS1];
    if (t < ROWS1) sf[t] = roipool_one(x, i0 + t);
    __syncthreads();

    const int j4 = blockIdx.x * 128 + t;
    float4 acc = make_float4(0.f, 0.f, 0.f, 0.f);
    const float4* __restrict__ w = W1 + (size_t)i0 * DH4 + j4;
    #pragma unroll 7
    for (int i = 0; i < ROWS1; i++) {
        const float4 v = __ldcs(&w[(size_t)i * DH4]);
        const float  s = sf[i];
        acc.x += s * v.x; acc.y += s * v.y;
        acc.z += s * v.z; acc.w += s * v.w;
    }
    g_part1[blockIdx.y * DH4 + j4] = acc;
}

// ---------------------------------------------------------------------------
// Kernel 3: reduce1. 64 blocks x 256 threads; 256 partials per output.
// ---------------------------------------------------------------------------
__global__ void k_reduce1(const float* __restrict__ b1)
{
    cudaGridDependencySynchronize();

    const int jl = threadIdx.x & 63;
    const int kq = threadIdx.x >> 6;
    const int j  = blockIdx.x * 64 + jl;
    const float* p1 = (const float*)g_part1;

    float s = 0.0f;
    #pragma unroll 8
    for (int k = 0; k < SPLIT1 / 4; k++)
        s += p1[(size_t)(kq * (SPLIT1 / 4) + k) * DH + j];

    __shared__ float sm[4][64];
    sm[kq][jl] = s;
    __syncthreads();
    if (kq == 0) {
        float t = sm[0][jl] + sm[1][jl] + sm[2][jl] + sm[3][jl] + b1[j];
        g_h1[j] = fmaxf(t, 0.0f);
    }
}

// ---------------------------------------------------------------------------
// Kernel 4: GEMV2 split-K with ReLU zero-skip (exact: ~50% of h1 is 0).
// grid (8, 256) = 2048 blocks, 128 threads. Block-uniform skip, 2KB rows.
// ---------------------------------------------------------------------------
__global__ void k_gemv2(const float4* __restrict__ W2)
{
    cudaGridDependencySynchronize();

    const int t  = threadIdx.x;
    const int j4 = blockIdx.x * 128 + t;
    const int i0 = blockIdx.y * ROWS2;

    __shared__ float sf[ROWS2];
    if (t < ROWS2) sf[t] = g_h1[i0 + t];
    __syncthreads();

    float4 acc = make_float4(0.f, 0.f, 0.f, 0.f);
    const float4* __restrict__ w = W2 + (size_t)i0 * DH4 + j4;
    #pragma unroll
    for (int i = 0; i < ROWS2; i++) {
        const float s = sf[i];
        if (s != 0.0f) {
            const float4 v = __ldcs(&w[(size_t)i * DH4]);
            acc.x += s * v.x; acc.y += s * v.y;
            acc.z += s * v.z; acc.w += s * v.w;
        }
    }
    g_part2[blockIdx.y * DH4 + j4] = acc;
}

// ---------------------------------------------------------------------------
// Kernel 5: fused reduce2 + heads partials. 64 blocks x 256 threads.
// Phase 1: block b builds its coalesced 64-entry fc7 slice from part2.
// Phase 2: 31 partial dot products against the (L2-prefetched) head weights.
// ---------------------------------------------------------------------------
__global__ void k_hred(const float* __restrict__ b2,
                       const float* __restrict__ Wloc,
                       const float* __restrict__ Wact)
{
    cudaGridDependencySynchronize();

    const int t  = threadIdx.x;
    const int j0 = blockIdx.x * 64;
    const float* p2 = (const float*)g_part2;

    __shared__ float sm[4][64];
    __shared__ float fc7s[64];

    {   // phase 1: fc7 slice (same layout as old reduce2, smem-combined)
        const int jl = t & 63;
        const int kq = t >> 6;
        const int j  = j0 + jl;
        float s = 0.0f;
        #pragma unroll 8
        for (int k = 0; k < SPLIT2 / 4; k++)
            s += p2[(size_t)(kq * (SPLIT2 / 4) + k) * DH + j];
        sm[kq][jl] = s;
        __syncthreads();
        if (kq == 0)
            fc7s[jl] = fmaxf(sm[0][jl] + sm[1][jl] + sm[2][jl] + sm[3][jl] + b2[j], 0.0f);
    }
    __syncthreads();

    // phase 2: partial dots. thread t -> (o = t/8, q = t%8), 8 terms each.
    __shared__ float sp[31][8];
    const int o = t >> 3;
    const int q = t & 7;
    if (o < 31) {
        float p = 0.0f;
        #pragma unroll
        for (int m = 0; m < 8; m++) {
            const int idx = q * 8 + m;
            const float f = fc7s[idx];
            p += (o < 4) ? f * Wloc[(j0 + idx) * 4 + o]
                         : f * Wact[(j0 + idx) * NACT + (o - 4)];
        }
        sp[o][q] = p;
    }
    __syncthreads();
    if (o < 31 && q == 0) {
        float s = 0.0f;
        #pragma unroll
        for (int m = 0; m < 8; m++) s += sp[o][m];
        g_hp[blockIdx.x * 31 + o] = s;
    }
}

// ---------------------------------------------------------------------------
// Kernel 6: final — sum head partials, gaussian object pick, assemble output.
// 1 block, 64 threads.
// ---------------------------------------------------------------------------
__global__ void k_final(const float* __restrict__ bloc,
                        const float* __restrict__ bact,
                        const int*   __restrict__ imgshape,
                        float* __restrict__ out)
{
    cudaGridDependencySynchronize();

    const int o = threadIdx.x;
    __shared__ float locs[4];

    if (o < 31) {
        float s = (o < 4) ? bloc[o] : bact[o - 4];
        #pragma unroll 8
        for (int b = 0; b < 64; b++) s += g_hp[b * 31 + o];
        if (o < 4) locs[o] = s;
        else       out[8 + (o - 4)] = s;    // action scores
    }
    __syncthreads();
    if (o != 0) return;

    const float img0 = (float)imgshape[0];
    const float img1 = (float)imgshape[1];

    const float hb0 = g_hbox[0], hb1 = g_hbox[1], hb2 = g_hbox[2], hb3 = g_hbox[3];
    const float hw_ = hb3 - hb1, hh_ = hb2 - hb0;
    const float h4x = 0.5f * hw_, h4y = 0.5f * hh_;
    const float hw = fmaxf(hw_, 1e-3f), hh = fmaxf(hh_, 1e-3f);

    const float mw = locs[3] - locs[1], mh = locs[2] - locs[0];
    const float mu0 = 0.5f * mw, mu1 = 0.5f * mh, mu2 = mw, mu3 = mh;

    float best = -1.0f;
    int   bl   = 0;
    for (int l = 0; l < 20; l++) {
        if (l == HUMAN_LBL) continue;
        const float b0 = g_kept[l][0], b1 = g_kept[l][1];
        const float b2 = g_kept[l][2], b3 = g_kept[l][3];
        const float cw_ = b3 - b1, ch_ = b2 - b0;
        const float cx = 0.5f * cw_, cy = 0.5f * ch_;
        const float cw = fmaxf(cw_, 1e-3f), ch = fmaxf(ch_, 1e-3f);
        const float d0 = (cx - h4x) / hw - mu0;
        const float d1 = (cy - h4y) / hh - mu1;
        const float d2 = logf(cw / hw) - mu2;
        const float d3 = logf(ch / hh) - mu3;
        const float gau = expf(-(d0*d0 + d1*d1 + d2*d2 + d3*d3) /
                               (2.0f * 0.3f * 0.3f));
        if (gau > best) { best = gau; bl = l; }
    }

    const float invy = img0 / (float)HFE;
    const float invx = img1 / (float)WFE;
    out[0] = hb0 * invy; out[1] = hb1 * invx;
    out[2] = hb2 * invy; out[3] = hb3 * invx;
    out[4] = g_kept[bl][0] * invy; out[5] = g_kept[bl][1] * invx;
    out[6] = g_kept[bl][2] * invy; out[7] = g_kept[bl][3] * invx;
    out[35] = (float)HFE / img0;
}

// ---------------------------------------------------------------------------
// PDL launch helper
// ---------------------------------------------------------------------------
static void launch_pdl(const void* func, dim3 grid, dim3 block, void** args)
{
    cudaLaunchConfig_t cfg = {};
    cfg.gridDim  = grid;
    cfg.blockDim = block;
    cudaLaunchAttribute attr[1];
    attr[0].id = cudaLaunchAttributeProgrammaticStreamSerialization;
    attr[0].val.programmaticStreamSerializationAllowed = 1;
    cfg.attrs = attr;
    cfg.numAttrs = 1;
    cudaLaunchKernelExC(&cfg, func, args);
}

// ---------------------------------------------------------------------------
extern "C" void kernel_launch(void* const* d_in, const int* in_sizes, int n_in,
                              void* d_out, int out_size)
{
    const float* x        = (const float*)d_in[0];
    const float* pscores  = (const float*)d_in[1];
    const float* poff     = (const float*)d_in[2];
    const float* rois     = (const float*)d_in[3];
    const int*   imgshape = (const int*)  d_in[4];
    const float* W1f      = (const float*)d_in[5];
    const float* b1       = (const float*)d_in[6];
    const float* W2f      = (const float*)d_in[7];
    const float* b2       = (const float*)d_in[8];
    const float* Wloc     = (const float*)d_in[9];
    const float* bloc     = (const float*)d_in[10];
    const float* Wact     = (const float*)d_in[11];
    const float* bact     = (const float*)d_in[12];
    float* out = (float*)d_out;
    const float4* W1 = (const float4*)W1f;
    const float4* W2 = (const float4*)W2f;

    {   void* a[] = {(void*)&pscores, (void*)&Wloc, (void*)&Wact};
        launch_pdl((const void*)k_selA, dim3(SELC, 21), dim3(256), a); }
    {   void* a[] = {(void*)&poff, (void*)&rois, (void*)&imgshape};
        launch_pdl((const void*)k_selB, dim3(1), dim3(32), a); }
    {   void* a[] = {(void*)&W1, (void*)&x};
        launch_pdl((const void*)k_gemv1, dim3(8, SPLIT1), dim3(128), a); }
    {   void* a[] = {(void*)&b1};
        launch_pdl((const void*)k_reduce1, dim3(64), dim3(256), a); }
    {   void* a[] = {(void*)&W2};
        launch_pdl((const void*)k_gemv2, dim3(8, SPLIT2), dim3(128), a); }
    {   void* a[] = {(void*)&b2, (void*)&Wloc, (void*)&Wact};
        launch_pdl((const void*)k_hred, dim3(64), dim3(256), a); }
    {   void* a[] = {(void*)&bloc, (void*)&bact, (void*)&imgshape, (void*)&out};
        launch_pdl((const void*)k_final, dim3(1), dim3(64), a); }
}

// round 11
// speedup vs baseline: 1.6298x; 1.0147x over previous
#include <cuda_runtime.h>
#include <math.h>

// ---------------- problem constants -----------------------------------------
#define R_ROIS 2000
#define NOBJ   21
#define HFE    38
#define WFE    50
#define D1     25088        // 512*7*7
#define DH     4096
#define DH4    (DH/4)
#define NACT   27
#define HUMAN_LBL 14

#define SPLIT1 256
#define ROWS1  (D1/SPLIT1)  // 98
#define SPLIT2 256
#define ROWS2  (DH/SPLIT2)  // 16
#define SELC   8            // roi chunks in select stage A

// ---------------- device scratch --------------------------------------------
__device__ float  g_selv[20][SELC];
__device__ int    g_seli[20][SELC];
__device__ float  g_kept[20][4];
__device__ float  g_hbox[4];
__device__ float4 g_part1[SPLIT1 * DH4];
__device__ float4 g_h1f4[DH4];
__device__ float4 g_part2[SPLIT2 * DH4];
__device__ float  g_hp[64 * 31];     // per-block head partials
__device__ float  g_sink[16];        // prefetch DCE guard

// ---------------------------------------------------------------------------
// Kernel 1a: select stage A — per-(label, roi-chunk) partial argmax of
// softmax prob (NMS_T=0 => greedy NMS keeps only the top-1 box per class).
// grid (SELC, 21): by<20 = labels; by==20 = Wloc/Wact L2 prefetch row.
// ---------------------------------------------------------------------------
__global__ void k_selA(const float* __restrict__ scores,
                       const float* __restrict__ Wloc,
                       const float* __restrict__ Wact)
{
    cudaGridDependencySynchronize();
    const int t = threadIdx.x;

    if (blockIdx.y == 20) {
        const float4* wl = (const float4*)Wloc;   // 4096 float4
        const float4* wa = (const float4*)Wact;   // 27648 float4
        float acc = 0.0f;
        for (int i = blockIdx.x * 256 + t; i < 4096;  i += SELC * 256) {
            const float4 v = __ldg(&wl[i]); acc += v.x + v.y + v.z + v.w;
        }
        for (int i = blockIdx.x * 256 + t; i < 27648; i += SELC * 256) {
            const float4 v = __ldg(&wa[i]); acc += v.x + v.y + v.z + v.w;
        }
        if (acc == 1e30f) g_sink[blockIdx.x] = acc;  // never true; defeats DCE
        return;
    }

    const int l   = blockIdx.y;
    const int cls = l + 1;
    const int r   = blockIdx.x * 256 + t;

    float best  = -1e30f;
    int   bestr = 0x7fffffff;
    if (r < R_ROIS) {
        const float* s = scores + r * NOBJ;
        float mx = s[0];
        #pragma unroll
        for (int j = 1; j < NOBJ; j++) mx = fmaxf(mx, s[j]);
        float sum = 0.0f;
        #pragma unroll
        for (int j = 0; j < NOBJ; j++) sum += expf(s[j] - mx);
        best  = s[cls] - (mx + logf(sum));
        bestr = r;
    }

    __shared__ float sb[256];
    __shared__ int   si[256];
    sb[t] = best; si[t] = bestr;
    __syncthreads();
    for (int st = 128; st > 0; st >>= 1) {
        if (t < st) {
            float ob = sb[t + st]; int oi = si[t + st];
            if (ob > sb[t] || (ob == sb[t] && oi < si[t])) { sb[t] = ob; si[t] = oi; }
        }
        __syncthreads();
    }
    if (t == 0) { g_selv[l][blockIdx.x] = sb[0]; g_seli[l][blockIdx.x] = si[0]; }
}

// ---------------------------------------------------------------------------
// Kernel 1b: select stage B — final argmax across chunks + box decode.
// ---------------------------------------------------------------------------
__global__ void k_selB(const float* __restrict__ off,
                       const float* __restrict__ rois,
                       const int*   __restrict__ imgshape)
{
    cudaGridDependencySynchronize();
    const int l = threadIdx.x;
    if (l >= 20) return;
    const int cls = l + 1;

    float best = -1e30f;
    int   r    = 0x7fffffff;
    #pragma unroll
    for (int c = 0; c < SELC; c++) {        // ascending chunks + strict >
        const float v = g_selv[l][c];       // == global first-max semantics
        if (v > best) { best = v; r = g_seli[l][c]; }
    }

    const float img0 = (float)imgshape[0];
    const float img1 = (float)imgshape[1];
    const float sy = (float)HFE / img0;
    const float sx = (float)WFE / img1;
    const float y1 = rois[r * 4 + 0] * sy;
    const float x1 = rois[r * 4 + 1] * sx;
    const float y2 = rois[r * 4 + 2] * sy;
    const float x2 = rois[r * 4 + 3] * sx;
    const float dy = off[r * (NOBJ * 4) + cls * 4 + 0] * 0.1f;
    const float dx = off[r * (NOBJ * 4) + cls * 4 + 1] * 0.1f;
    const float dh = off[r * (NOBJ * 4) + cls * 4 + 2] * 0.2f;
    const float dw = off[r * (NOBJ * 4) + cls * 4 + 3] * 0.2f;
    const float h  = y2 - y1, w = x2 - x1;
    const float cy = y1 + 0.5f * h, cx = x1 + 0.5f * w;
    const float cy2 = dy * h + cy, cx2 = dx * w + cx;
    const float h2 = expf(dh) * h, w2 = expf(dw) * w;
    float by1 = fminf(fmaxf(cy2 - 0.5f * h2, 0.0f), (float)HFE);
    float bx1 = fminf(fmaxf(cx2 - 0.5f * w2, 0.0f), (float)WFE);
    float by2 = fminf(fmaxf(cy2 + 0.5f * h2, 0.0f), (float)HFE);
    float bx2 = fminf(fmaxf(cx2 + 0.5f * w2, 0.0f), (float)WFE);
    g_kept[l][0] = by1; g_kept[l][1] = bx1;
    g_kept[l][2] = by2; g_kept[l][3] = bx2;
    if (l == HUMAN_LBL) {
        g_hbox[0] = by1; g_hbox[1] = bx1;
        g_hbox[2] = by2; g_hbox[3] = bx2;
    }
}

// ---------------------------------------------------------------------------
// roipool for one output element (same math as reference)
// ---------------------------------------------------------------------------
__device__ __forceinline__ float roipool_one(const float* __restrict__ x, int idx)
{
    const int c  = idx / 49;
    const int ph = (idx % 49) / 7;
    const int pw = idx % 7;

    const float y1 = g_hbox[0], x1 = g_hbox[1], y2 = g_hbox[2], x2 = g_hbox[3];
    const int xmin = (int)rintf(x1 * 0.0625f);
    const int ymin = (int)rintf(y1 * 0.0625f);
    const int xmax = (int)rintf(x2 * 0.0625f);
    const int ymax = (int)rintf(y2 * 0.0625f);
    const float rw = (float)max(xmax - xmin + 1, 1);
    const float rh = (float)max(ymax - ymin + 1, 1);

    int hs = ymin + (int)floorf((float)ph * rh / 7.0f);
    int he = ymin + (int)ceilf((float)(ph + 1) * rh / 7.0f);
    int ws = xmin + (int)floorf((float)pw * rw / 7.0f);
    int we = xmin + (int)ceilf((float)(pw + 1) * rw / 7.0f);
    hs = min(max(hs, 0), HFE); he = min(max(he, 0), HFE);
    ws = min(max(ws, 0), WFE); we = min(max(we, 0), WFE);

    float m = -1e30f;
    for (int yy = hs; yy < he; yy++)
        for (int xx = ws; xx < we; xx++)
            m = fmaxf(m, x[c * (HFE * WFE) + yy * WFE + xx]);
    return (hs < he && ws < we) ? ((m <= -0.5e30f) ? 0.0f : m) : 0.0f;
}

// ---------------------------------------------------------------------------
// Kernel 2: GEMV1 split-K with fused roipool prologue.
// grid (8, 256) = 2048 blocks, 128 threads. W1 streamed evict-first.
// ---------------------------------------------------------------------------
__global__ void k_gemv1(const float4* __restrict__ W1,
                        const float*  __restrict__ x)
{
    cudaGridDependencySynchronize();

    const int t  = threadIdx.x;
    const int i0 = blockIdx.y * ROWS1;

    __shared__ float sf[ROWS1];
    if (t < ROWS1) sf[t] = roipool_one(x, i0 + t);
    __syncthreads();

    const int j4 = blockIdx.x * 128 + t;
    float4 acc = make_float4(0.f, 0.f, 0.f, 0.f);
    const float4* __restrict__ w = W1 + (size_t)i0 * DH4 + j4;
    #pragma unroll 7
    for (int i = 0; i < ROWS1; i++) {
        const float4 v = __ldcs(&w[(size_t)i * DH4]);
        const float  s = sf[i];
        acc.x += s * v.x; acc.y += s * v.y;
        acc.z += s * v.z; acc.w += s * v.w;
    }
    g_part1[blockIdx.y * DH4 + j4] = acc;
}

// ---------------------------------------------------------------------------
// Kernel 3: reduce1, high-MLP float4 version.
// 64 blocks x 256 threads. Block covers 16 float4 (64 floats) of j.
// Thread (jl4 = t&15, kq = t>>4) sums 16 fully-unrolled float4 partials
// => ~4MB outstanding chip-wide: BW-limited, not latency-limited.
// ---------------------------------------------------------------------------
__global__ void k_reduce1(const float4* __restrict__ b1)
{
    cudaGridDependencySynchronize();

    const int t   = threadIdx.x;
    const int jl4 = t & 15;
    const int kq  = t >> 4;                  // 0..15
    const int j4  = blockIdx.x * 16 + jl4;

    float4 a = make_float4(0.f, 0.f, 0.f, 0.f);
    #pragma unroll
    for (int k = 0; k < SPLIT1 / 16; k++) {  // 16 independent loads
        const float4 v = g_part1[(size_t)(kq * (SPLIT1 / 16) + k) * DH4 + j4];
        a.x += v.x; a.y += v.y; a.z += v.z; a.w += v.w;
    }

    __shared__ float4 sm[16][16];
    sm[kq][jl4] = a;
    __syncthreads();

    if (t < 16) {
        const int jj4 = blockIdx.x * 16 + t;
        float4 s = b1[jj4];
        #pragma unroll
        for (int q = 0; q < 16; q++) {
            const float4 v = sm[q][t];
            s.x += v.x; s.y += v.y; s.z += v.z; s.w += v.w;
        }
        s.x = fmaxf(s.x, 0.f); s.y = fmaxf(s.y, 0.f);
        s.z = fmaxf(s.z, 0.f); s.w = fmaxf(s.w, 0.f);
        g_h1f4[jj4] = s;
    }
}

// ---------------------------------------------------------------------------
// Kernel 4: GEMV2 split-K with ReLU zero-skip (exact: ~50% of h1 is 0).
// grid (8, 256) = 2048 blocks, 128 threads. Block-uniform skip, 2KB rows.
// ---------------------------------------------------------------------------
__global__ void k_gemv2(const float4* __restrict__ W2)
{
    cudaGridDependencySynchronize();

    const int t  = threadIdx.x;
    const int j4 = blockIdx.x * 128 + t;
    const int i0 = blockIdx.y * ROWS2;
    const float* h1 = (const float*)g_h1f4;

    __shared__ float sf[ROWS2];
    if (t < ROWS2) sf[t] = h1[i0 + t];
    __syncthreads();

    float4 acc = make_float4(0.f, 0.f, 0.f, 0.f);
    const float4* __restrict__ w = W2 + (size_t)i0 * DH4 + j4;
    #pragma unroll
    for (int i = 0; i < ROWS2; i++) {
        const float s = sf[i];
        if (s != 0.0f) {
            const float4 v = __ldcs(&w[(size_t)i * DH4]);
            acc.x += s * v.x; acc.y += s * v.y;
            acc.z += s * v.z; acc.w += s * v.w;
        }
    }
    g_part2[blockIdx.y * DH4 + j4] = acc;
}

// ---------------------------------------------------------------------------
// Kernel 5: fused reduce2 + heads partials. 64 blocks x 256 threads.
// Phase 1: high-MLP float4 rebuild of the block's 64-entry fc7 slice.
// Phase 2: 31 partial dot products against (L2-prefetched) head weights.
// ---------------------------------------------------------------------------
__global__ void k_hred(const float4* __restrict__ b2,
                       const float* __restrict__ Wloc,
                       const float* __restrict__ Wact)
{
    cudaGridDependencySynchronize();

    const int t  = threadIdx.x;
    const int j0 = blockIdx.x * 64;

    __shared__ float4 sm4[16][16];
    __shared__ float  fc7s[64];

    {   // phase 1: thread (jl4=t&15, kq=t>>4) sums 16 float4 partials
        const int jl4 = t & 15;
        const int kq  = t >> 4;
        const int j4  = blockIdx.x * 16 + jl4;
        float4 a = make_float4(0.f, 0.f, 0.f, 0.f);
        #pragma unroll
        for (int k = 0; k < SPLIT2 / 16; k++) {
            const float4 v = g_part2[(size_t)(kq * (SPLIT2 / 16) + k) * DH4 + j4];
            a.x += v.x; a.y += v.y; a.z += v.z; a.w += v.w;
        }
        sm4[kq][jl4] = a;
    }
    __syncthreads();
    if (t < 16) {
        const int j4 = blockIdx.x * 16 + t;
        float4 s = b2[j4];
        #pragma unroll
        for (int q = 0; q < 16; q++) {
            const float4 v = sm4[q][t];
            s.x += v.x; s.y += v.y; s.z += v.z; s.w += v.w;
        }
        fc7s[t * 4 + 0] = fmaxf(s.x, 0.f);
        fc7s[t * 4 + 1] = fmaxf(s.y, 0.f);
        fc7s[t * 4 + 2] = fmaxf(s.z, 0.f);
        fc7s[t * 4 + 3] = fmaxf(s.w, 0.f);
    }
    __syncthreads();

    // phase 2: partial dots. thread t -> (o = t/8, q = t%8), 8 terms each.
    __shared__ float sp[31][8];
    const int o = t >> 3;
    const int q = t & 7;
    if (o < 31) {
        float p = 0.0f;
        #pragma unroll
        for (int m = 0; m < 8; m++) {
            const int idx = q * 8 + m;
            const float f = fc7s[idx];
            p += (o < 4) ? f * Wloc[(j0 + idx) * 4 + o]
                         : f * Wact[(j0 + idx) * NACT + (o - 4)];
        }
        sp[o][q] = p;
    }
    __syncthreads();
    if (o < 31 && q == 0) {
        float s = 0.0f;
        #pragma unroll
        for (int m = 0; m < 8; m++) s += sp[o][m];
        g_hp[blockIdx.x * 31 + o] = s;
    }
}

// ---------------------------------------------------------------------------
// Kernel 6: final — sum head partials, gaussian object pick, assemble output.
// ---------------------------------------------------------------------------
__global__ void k_final(const float* __restrict__ bloc,
                        const float* __restrict__ bact,
                        const int*   __restrict__ imgshape,
                        float* __restrict__ out)
{
    cudaGridDependencySynchronize();

    const int o = threadIdx.x;
    __shared__ float locs[4];

    if (o < 31) {
        float s = (o < 4) ? bloc[o] : bact[o - 4];
        #pragma unroll 8
        for (int b = 0; b < 64; b++) s += g_hp[b * 31 + o];
        if (o < 4) locs[o] = s;
        else       out[8 + (o - 4)] = s;    // action scores
    }
    __syncthreads();
    if (o != 0) return;

    const float img0 = (float)imgshape[0];
    const float img1 = (float)imgshape[1];

    const float hb0 = g_hbox[0], hb1 = g_hbox[1], hb2 = g_hbox[2], hb3 = g_hbox[3];
    const float hw_ = hb3 - hb1, hh_ = hb2 - hb0;
    const float h4x = 0.5f * hw_, h4y = 0.5f * hh_;
    const float hw = fmaxf(hw_, 1e-3f), hh = fmaxf(hh_, 1e-3f);

    const float mw = locs[3] - locs[1], mh = locs[2] - locs[0];
    const float mu0 = 0.5f * mw, mu1 = 0.5f * mh, mu2 = mw, mu3 = mh;

    float best = -1.0f;
    int   bl   = 0;
    for (int l = 0; l < 20; l++) {
        if (l == HUMAN_LBL) continue;
        const float b0 = g_kept[l][0], b1 = g_kept[l][1];
        const float b2 = g_kept[l][2], b3 = g_kept[l][3];
        const float cw_ = b3 - b1, ch_ = b2 - b0;
        const float cx = 0.5f * cw_, cy = 0.5f * ch_;
        const float cw = fmaxf(cw_, 1e-3f), ch = fmaxf(ch_, 1e-3f);
        const float d0 = (cx - h4x) / hw - mu0;
        const float d1 = (cy - h4y) / hh - mu1;
        const float d2 = logf(cw / hw) - mu2;
        const float d3 = logf(ch / hh) - mu3;
        const float gau = expf(-(d0*d0 + d1*d1 + d2*d2 + d3*d3) /
                               (2.0f * 0.3f * 0.3f));
        if (gau > best) { best = gau; bl = l; }
    }

    const float invy = img0 / (float)HFE;
    const float invx = img1 / (float)WFE;
    out[0] = hb0 * invy; out[1] = hb1 * invx;
    out[2] = hb2 * invy; out[3] = hb3 * invx;
    out[4] = g_kept[bl][0] * invy; out[5] = g_kept[bl][1] * invx;
    out[6] = g_kept[bl][2] * invy; out[7] = g_kept[bl][3] * invx;
    out[35] = (float)HFE / img0;
}

// ---------------------------------------------------------------------------
// PDL launch helper
// ---------------------------------------------------------------------------
static void launch_pdl(const void* func, dim3 grid, dim3 block, void** args)
{
    cudaLaunchConfig_t cfg = {};
    cfg.gridDim  = grid;
    cfg.blockDim = block;
    cudaLaunchAttribute attr[1];
    attr[0].id = cudaLaunchAttributeProgrammaticStreamSerialization;
    attr[0].val.programmaticStreamSerializationAllowed = 1;
    cfg.attrs = attr;
    cfg.numAttrs = 1;
    cudaLaunchKernelExC(&cfg, func, args);
}

// ---------------------------------------------------------------------------
extern "C" void kernel_launch(void* const* d_in, const int* in_sizes, int n_in,
                              void* d_out, int out_size)
{
    const float* x        = (const float*)d_in[0];
    const float* pscores  = (const float*)d_in[1];
    const float* poff     = (const float*)d_in[2];
    const float* rois     = (const float*)d_in[3];
    const int*   imgshape = (const int*)  d_in[4];
    const float* W1f      = (const float*)d_in[5];
    const float* b1f      = (const float*)d_in[6];
    const float* W2f      = (const float*)d_in[7];
    const float* b2f      = (const float*)d_in[8];
    const float* Wloc     = (const float*)d_in[9];
    const float* bloc     = (const float*)d_in[10];
    const float* Wact     = (const float*)d_in[11];
    const float* bact     = (const float*)d_in[12];
    float* out = (float*)d_out;
    const float4* W1 = (const float4*)W1f;
    const float4* W2 = (const float4*)W2f;
    const float4* b1 = (const float4*)b1f;
    const float4* b2 = (const float4*)b2f;

    {   void* a[] = {(void*)&pscores, (void*)&Wloc, (void*)&Wact};
        launch_pdl((const void*)k_selA, dim3(SELC, 21), dim3(256), a); }
    {   void* a[] = {(void*)&poff, (void*)&rois, (void*)&imgshape};
        launch_pdl((const void*)k_selB, dim3(1), dim3(32), a); }
    {   void* a[] = {(void*)&W1, (void*)&x};
        launch_pdl((const void*)k_gemv1, dim3(8, SPLIT1), dim3(128), a); }
    {   void* a[] = {(void*)&b1};
        launch_pdl((const void*)k_reduce1, dim3(64), dim3(256), a); }
    {   void* a[] = {(void*)&W2};
        launch_pdl((const void*)k_gemv2, dim3(8, SPLIT2), dim3(128), a); }
    {   void* a[] = {(void*)&b2, (void*)&Wloc, (void*)&Wact};
        launch_pdl((const void*)k_hred, dim3(64), dim3(256), a); }
    {   void* a[] = {(void*)&bloc, (void*)&bact, (void*)&imgshape, (void*)&out};
        launch_pdl((const void*)k_final, dim3(1), dim3(64), a); }
}

// round 12
// speedup vs baseline: 1.6421x; 1.0076x over previous
#include <cuda_runtime.h>
#include <math.h>

// ---------------- problem constants -----------------------------------------
#define R_ROIS 2000
#define NOBJ   21
#define HFE    38
#define WFE    50
#define D1     25088        // 512*7*7
#define DH     4096
#define DH4    (DH/4)
#define NACT   27
#define HUMAN_LBL 14

#define SPLIT1 256
#define ROWS1  (D1/SPLIT1)  // 98
#define SPLIT2 256
#define ROWS2  (DH/SPLIT2)  // 16
#define SELC   8            // roi chunks in select stage A
#define HB     256          // hred blocks

// ---------------- device scratch --------------------------------------------
__device__ float  g_selv[20][SELC];
__device__ int    g_seli[20][SELC];
__device__ float  g_kept[20][4];
__device__ float  g_hbox[4];
__device__ float4 g_part1[SPLIT1 * DH4];
__device__ float4 g_h1f4[DH4];
__device__ float4 g_part2[SPLIT2 * DH4];
__device__ float  g_hp[HB * 31];     // per-block head partials
__device__ float  g_sink[16];        // prefetch DCE guard

// ---------------------------------------------------------------------------
// Kernel 1a: select stage A — per-(label, roi-chunk) partial argmax of
// softmax prob (NMS_T=0 => greedy NMS keeps only the top-1 box per class).
// grid (SELC, 21): by<20 = labels; by==20 = Wloc/Wact L2 prefetch row.
// ---------------------------------------------------------------------------
__global__ void k_selA(const float* __restrict__ scores,
                       const float* __restrict__ Wloc,
                       const float* __restrict__ Wact)
{
    cudaGridDependencySynchronize();
    const int t = threadIdx.x;

    if (blockIdx.y == 20) {
        const float4* wl = (const float4*)Wloc;   // 4096 float4
        const float4* wa = (const float4*)Wact;   // 27648 float4
        float acc = 0.0f;
        for (int i = blockIdx.x * 256 + t; i < 4096;  i += SELC * 256) {
            const float4 v = __ldg(&wl[i]); acc += v.x + v.y + v.z + v.w;
        }
        for (int i = blockIdx.x * 256 + t; i < 27648; i += SELC * 256) {
            const float4 v = __ldg(&wa[i]); acc += v.x + v.y + v.z + v.w;
        }
        if (acc == 1e30f) g_sink[blockIdx.x] = acc;  // never true; defeats DCE
        return;
    }

    const int l   = blockIdx.y;
    const int cls = l + 1;
    const int r   = blockIdx.x * 256 + t;

    float best  = -1e30f;
    int   bestr = 0x7fffffff;
    if (r < R_ROIS) {
        const float* s = scores + r * NOBJ;
        float mx = s[0];
        #pragma unroll
        for (int j = 1; j < NOBJ; j++) mx = fmaxf(mx, s[j]);
        float sum = 0.0f;
        #pragma unroll
        for (int j = 0; j < NOBJ; j++) sum += expf(s[j] - mx);
        best  = s[cls] - (mx + logf(sum));
        bestr = r;
    }

    __shared__ float sb[256];
    __shared__ int   si[256];
    sb[t] = best; si[t] = bestr;
    __syncthreads();
    for (int st = 128; st > 0; st >>= 1) {
        if (t < st) {
            float ob = sb[t + st]; int oi = si[t + st];
            if (ob > sb[t] || (ob == sb[t] && oi < si[t])) { sb[t] = ob; si[t] = oi; }
        }
        __syncthreads();
    }
    if (t == 0) { g_selv[l][blockIdx.x] = sb[0]; g_seli[l][blockIdx.x] = si[0]; }
}

// ---------------------------------------------------------------------------
// Kernel 1b: select stage B — final argmax across chunks + box decode.
// ---------------------------------------------------------------------------
__global__ void k_selB(const float* __restrict__ off,
                       const float* __restrict__ rois,
                       const int*   __restrict__ imgshape)
{
    cudaGridDependencySynchronize();
    const int l = threadIdx.x;
    if (l >= 20) return;
    const int cls = l + 1;

    float best = -1e30f;
    int   r    = 0x7fffffff;
    #pragma unroll
    for (int c = 0; c < SELC; c++) {        // ascending chunks + strict >
        const float v = g_selv[l][c];       // == global first-max semantics
        if (v > best) { best = v; r = g_seli[l][c]; }
    }

    const float img0 = (float)imgshape[0];
    const float img1 = (float)imgshape[1];
    const float sy = (float)HFE / img0;
    const float sx = (float)WFE / img1;
    const float y1 = rois[r * 4 + 0] * sy;
    const float x1 = rois[r * 4 + 1] * sx;
    const float y2 = rois[r * 4 + 2] * sy;
    const float x2 = rois[r * 4 + 3] * sx;
    const float dy = off[r * (NOBJ * 4) + cls * 4 + 0] * 0.1f;
    const float dx = off[r * (NOBJ * 4) + cls * 4 + 1] * 0.1f;
    const float dh = off[r * (NOBJ * 4) + cls * 4 + 2] * 0.2f;
    const float dw = off[r * (NOBJ * 4) + cls * 4 + 3] * 0.2f;
    const float h  = y2 - y1, w = x2 - x1;
    const float cy = y1 + 0.5f * h, cx = x1 + 0.5f * w;
    const float cy2 = dy * h + cy, cx2 = dx * w + cx;
    const float h2 = expf(dh) * h, w2 = expf(dw) * w;
    float by1 = fminf(fmaxf(cy2 - 0.5f * h2, 0.0f), (float)HFE);
    float bx1 = fminf(fmaxf(cx2 - 0.5f * w2, 0.0f), (float)WFE);
    float by2 = fminf(fmaxf(cy2 + 0.5f * h2, 0.0f), (float)HFE);
    float bx2 = fminf(fmaxf(cx2 + 0.5f * w2, 0.0f), (float)WFE);
    g_kept[l][0] = by1; g_kept[l][1] = bx1;
    g_kept[l][2] = by2; g_kept[l][3] = bx2;
    if (l == HUMAN_LBL) {
        g_hbox[0] = by1; g_hbox[1] = bx1;
        g_hbox[2] = by2; g_hbox[3] = bx2;
    }
}

// ---------------------------------------------------------------------------
// roipool for one output element (same math as reference)
// ---------------------------------------------------------------------------
__device__ __forceinline__ float roipool_one(const float* __restrict__ x, int idx)
{
    const int c  = idx / 49;
    const int ph = (idx % 49) / 7;
    const int pw = idx % 7;

    const float y1 = g_hbox[0], x1 = g_hbox[1], y2 = g_hbox[2], x2 = g_hbox[3];
    const int xmin = (int)rintf(x1 * 0.0625f);
    const int ymin = (int)rintf(y1 * 0.0625f);
    const int xmax = (int)rintf(x2 * 0.0625f);
    const int ymax = (int)rintf(y2 * 0.0625f);
    const float rw = (float)max(xmax - xmin + 1, 1);
    const float rh = (float)max(ymax - ymin + 1, 1);

    int hs = ymin + (int)floorf((float)ph * rh / 7.0f);
    int he = ymin + (int)ceilf((float)(ph + 1) * rh / 7.0f);
    int ws = xmin + (int)floorf((float)pw * rw / 7.0f);
    int we = xmin + (int)ceilf((float)(pw + 1) * rw / 7.0f);
    hs = min(max(hs, 0), HFE); he = min(max(he, 0), HFE);
    ws = min(max(ws, 0), WFE); we = min(max(we, 0), WFE);

    float m = -1e30f;
    for (int yy = hs; yy < he; yy++)
        for (int xx = ws; xx < we; xx++)
            m = fmaxf(m, x[c * (HFE * WFE) + yy * WFE + xx]);
    return (hs < he && ws < we) ? ((m <= -0.5e30f) ? 0.0f : m) : 0.0f;
}

// ---------------------------------------------------------------------------
// Kernel 2: GEMV1 split-K with fused roipool prologue.
// grid (8, 256) = 2048 blocks, 128 threads. W1 streamed evict-first.
// ---------------------------------------------------------------------------
__global__ void k_gemv1(const float4* __restrict__ W1,
                        const float*  __restrict__ x)
{
    cudaGridDependencySynchronize();

    const int t  = threadIdx.x;
    const int i0 = blockIdx.y * ROWS1;

    __shared__ float sf[ROWS1];
    if (t < ROWS1) sf[t] = roipool_one(x, i0 + t);
    __syncthreads();

    const int j4 = blockIdx.x * 128 + t;
    float4 acc = make_float4(0.f, 0.f, 0.f, 0.f);
    const float4* __restrict__ w = W1 + (size_t)i0 * DH4 + j4;
    #pragma unroll 7
    for (int i = 0; i < ROWS1; i++) {
        const float4 v = __ldcs(&w[(size_t)i * DH4]);
        const float  s = sf[i];
        acc.x += s * v.x; acc.y += s * v.y;
        acc.z += s * v.z; acc.w += s * v.w;
    }
    g_part1[blockIdx.y * DH4 + j4] = acc;
}

// ---------------------------------------------------------------------------
// Kernel 3: reduce1, block-spread version. 256 blocks x 256 threads.
// Block owns 4 float4 columns. Thread (jl4 = t&3, kq = t>>2) sums 4 partials
// (fits the register budget); 6-step smem tree over the 64 kq groups.
// ---------------------------------------------------------------------------
__global__ void k_reduce1(const float4* __restrict__ b1)
{
    cudaGridDependencySynchronize();

    const int t   = threadIdx.x;
    const int jl4 = t & 3;
    const int kq  = t >> 2;                  // 0..63
    const int j4  = blockIdx.x * 4 + jl4;

    float4 a = make_float4(0.f, 0.f, 0.f, 0.f);
    #pragma unroll
    for (int k = 0; k < SPLIT1 / 64; k++) {  // 4 independent loads
        const float4 v = g_part1[(size_t)(kq * (SPLIT1 / 64) + k) * DH4 + j4];
        a.x += v.x; a.y += v.y; a.z += v.z; a.w += v.w;
    }

    __shared__ float4 sm[64][4];
    sm[kq][jl4] = a;
    __syncthreads();
    for (int st = 32; st >= 1; st >>= 1) {
        if (kq < st) {
            const float4 v = sm[kq + st][jl4];
            sm[kq][jl4].x += v.x; sm[kq][jl4].y += v.y;
            sm[kq][jl4].z += v.z; sm[kq][jl4].w += v.w;
        }
        __syncthreads();
    }

    if (t < 4) {
        const int jj4 = blockIdx.x * 4 + t;
        float4 s = b1[jj4];
        const float4 v = sm[0][t];
        s.x = fmaxf(s.x + v.x, 0.f); s.y = fmaxf(s.y + v.y, 0.f);
        s.z = fmaxf(s.z + v.z, 0.f); s.w = fmaxf(s.w + v.w, 0.f);
        g_h1f4[jj4] = s;
    }
}

// ---------------------------------------------------------------------------
// Kernel 4: GEMV2 split-K with ReLU zero-skip (exact: ~50% of h1 is 0).
// grid (8, 256) = 2048 blocks, 128 threads. Block-uniform skip, 2KB rows.
// ---------------------------------------------------------------------------
__global__ void k_gemv2(const float4* __restrict__ W2)
{
    cudaGridDependencySynchronize();

    const int t  = threadIdx.x;
    const int j4 = blockIdx.x * 128 + t;
    const int i0 = blockIdx.y * ROWS2;
    const float* h1 = (const float*)g_h1f4;

    __shared__ float sf[ROWS2];
    if (t < ROWS2) sf[t] = h1[i0 + t];
    __syncthreads();

    float4 acc = make_float4(0.f, 0.f, 0.f, 0.f);
    const float4* __restrict__ w = W2 + (size_t)i0 * DH4 + j4;
    #pragma unroll
    for (int i = 0; i < ROWS2; i++) {
        const float s = sf[i];
        if (s != 0.0f) {
            const float4 v = __ldcs(&w[(size_t)i * DH4]);
            acc.x += s * v.x; acc.y += s * v.y;
            acc.z += s * v.z; acc.w += s * v.w;
        }
    }
    g_part2[blockIdx.y * DH4 + j4] = acc;
}

// ---------------------------------------------------------------------------
// Kernel 5: fused reduce2 + heads partials. 256 blocks x 256 threads.
// Phase 1: block-spread rebuild of a 16-entry fc7 slice (4 float4 columns).
// Phase 2: 31 partial dot products against the (L2-prefetched) head weights.
// ---------------------------------------------------------------------------
__global__ void k_hred(const float4* __restrict__ b2,
                       const float* __restrict__ Wloc,
                       const float* __restrict__ Wact)
{
    cudaGridDependencySynchronize();

    const int t  = threadIdx.x;
    const int j0 = blockIdx.x * 16;          // first fc7 index of this block

    __shared__ float4 sm4[64][4];
    __shared__ float  fc7s[16];

    {   // phase 1: thread (jl4 = t&3, kq = t>>2) sums 4 float4 partials
        const int jl4 = t & 3;
        const int kq  = t >> 2;
        const int j4  = blockIdx.x * 4 + jl4;
        float4 a = make_float4(0.f, 0.f, 0.f, 0.f);
        #pragma unroll
        for (int k = 0; k < SPLIT2 / 64; k++) {
            const float4 v = g_part2[(size_t)(kq * (SPLIT2 / 64) + k) * DH4 + j4];
            a.x += v.x; a.y += v.y; a.z += v.z; a.w += v.w;
        }
        sm4[kq][jl4] = a;
    }
    __syncthreads();
    {
        const int jl4 = t & 3;
        const int kq  = t >> 2;
        for (int st = 32; st >= 1; st >>= 1) {
            if (kq < st) {
                const float4 v = sm4[kq + st][jl4];
                sm4[kq][jl4].x += v.x; sm4[kq][jl4].y += v.y;
                sm4[kq][jl4].z += v.z; sm4[kq][jl4].w += v.w;
            }
            __syncthreads();
        }
    }
    if (t < 4) {
        const int j4 = blockIdx.x * 4 + t;
        float4 s = b2[j4];
        const float4 v = sm4[0][t];
        fc7s[t * 4 + 0] = fmaxf(s.x + v.x, 0.f);
        fc7s[t * 4 + 1] = fmaxf(s.y + v.y, 0.f);
        fc7s[t * 4 + 2] = fmaxf(s.z + v.z, 0.f);
        fc7s[t * 4 + 3] = fmaxf(s.w + v.w, 0.f);
    }
    __syncthreads();

    // phase 2: partial dots. thread t -> (o = t/8, q = t%8), 2 terms each.
    __shared__ float sp[31][8];
    const int o = t >> 3;
    const int q = t & 7;
    if (o < 31) {
        float p = 0.0f;
        #pragma unroll
        for (int m = 0; m < 2; m++) {
            const int idx = q * 2 + m;
            const float f = fc7s[idx];
            p += (o < 4) ? f * Wloc[(j0 + idx) * 4 + o]
                         : f * Wact[(j0 + idx) * NACT + (o - 4)];
        }
        sp[o][q] = p;
    }
    __syncthreads();
    if (o < 31 && q == 0) {
        float s = 0.0f;
        #pragma unroll
        for (int m = 0; m < 8; m++) s += sp[o][m];
        g_hp[blockIdx.x * 31 + o] = s;
    }
}

// ---------------------------------------------------------------------------
// Kernel 6: final — sum head partials (2-stage), gaussian pick, assemble.
// 1 block, 256 threads: (o = t&31, chunk = t>>5) covers 31 outputs x 8 chunks.
// ---------------------------------------------------------------------------
__global__ void k_final(const float* __restrict__ bloc,
                        const float* __restrict__ bact,
                        const int*   __restrict__ imgshape,
                        float* __restrict__ out)
{
    cudaGridDependencySynchronize();

    const int t = threadIdx.x;
    const int o = t & 31;
    const int c = t >> 5;                    // 0..7
    __shared__ float sp2[8][32];
    __shared__ float locs[4];

    {
        float s = 0.0f;
        if (o < 31) {
            #pragma unroll 4
            for (int b = c * (HB / 8); b < (c + 1) * (HB / 8); b++)
                s += g_hp[b * 31 + o];
        }
        sp2[c][o] = s;
    }
    __syncthreads();
    if (t < 31) {
        float s = (t < 4) ? bloc[t] : bact[t - 4];
        #pragma unroll
        for (int m = 0; m < 8; m++) s += sp2[m][t];
        if (t < 4) locs[t] = s;
        else       out[8 + (t - 4)] = s;     // action scores
    }
    __syncthreads();
    if (t != 0) return;

    const float img0 = (float)imgshape[0];
    const float img1 = (float)imgshape[1];

    const float hb0 = g_hbox[0], hb1 = g_hbox[1], hb2 = g_hbox[2], hb3 = g_hbox[3];
    const float hw_ = hb3 - hb1, hh_ = hb2 - hb0;
    const float h4x = 0.5f * hw_, h4y = 0.5f * hh_;
    const float hw = fmaxf(hw_, 1e-3f), hh = fmaxf(hh_, 1e-3f);

    const float mw = locs[3] - locs[1], mh = locs[2] - locs[0];
    const float mu0 = 0.5f * mw, mu1 = 0.5f * mh, mu2 = mw, mu3 = mh;

    float best = -1.0f;
    int   bl   = 0;
    for (int l = 0; l < 20; l++) {
        if (l == HUMAN_LBL) continue;
        const float b0 = g_kept[l][0], b1 = g_kept[l][1];
        const float b2 = g_kept[l][2], b3 = g_kept[l][3];
        const float cw_ = b3 - b1, ch_ = b2 - b0;
        const float cx = 0.5f * cw_, cy = 0.5f * ch_;
        const float cw = fmaxf(cw_, 1e-3f), ch = fmaxf(ch_, 1e-3f);
        const float d0 = (cx - h4x) / hw - mu0;
        const float d1 = (cy - h4y) / hh - mu1;
        const float d2 = logf(cw / hw) - mu2;
        const float d3 = logf(ch / hh) - mu3;
        const float gau = expf(-(d0*d0 + d1*d1 + d2*d2 + d3*d3) /
                               (2.0f * 0.3f * 0.3f));
        if (gau > best) { best = gau; bl = l; }
    }

    const float invy = img0 / (float)HFE;
    const float invx = img1 / (float)WFE;
    out[0] = hb0 * invy; out[1] = hb1 * invx;
    out[2] = hb2 * invy; out[3] = hb3 * invx;
    out[4] = g_kept[bl][0] * invy; out[5] = g_kept[bl][1] * invx;
    out[6] = g_kept[bl][2] * invy; out[7] = g_kept[bl][3] * invx;
    out[35] = (float)HFE / img0;
}

// ---------------------------------------------------------------------------
// PDL launch helper
// ---------------------------------------------------------------------------
static void launch_pdl(const void* func, dim3 grid, dim3 block, void** args)
{
    cudaLaunchConfig_t cfg = {};
    cfg.gridDim  = grid;
    cfg.blockDim = block;
    cudaLaunchAttribute attr[1];
    attr[0].id = cudaLaunchAttributeProgrammaticStreamSerialization;
    attr[0].val.programmaticStreamSerializationAllowed = 1;
    cfg.attrs = attr;
    cfg.numAttrs = 1;
    cudaLaunchKernelExC(&cfg, func, args);
}

// ---------------------------------------------------------------------------
extern "C" void kernel_launch(void* const* d_in, const int* in_sizes, int n_in,
                              void* d_out, int out_size)
{
    const float* x        = (const float*)d_in[0];
    const float* pscores  = (const float*)d_in[1];
    const float* poff     = (const float*)d_in[2];
    const float* rois     = (const float*)d_in[3];
    const int*   imgshape = (const int*)  d_in[4];
    const float* W1f      = (const float*)d_in[5];
    const float* b1f      = (const float*)d_in[6];
    const float* W2f      = (const float*)d_in[7];
    const float* b2f      = (const float*)d_in[8];
    const float* Wloc     = (const float*)d_in[9];
    const float* bloc     = (const float*)d_in[10];
    const float* Wact     = (const float*)d_in[11];
    const float* bact     = (const float*)d_in[12];
    float* out = (float*)d_out;
    const float4* W1 = (const float4*)W1f;
    const float4* W2 = (const float4*)W2f;
    const float4* b1 = (const float4*)b1f;
    const float4* b2 = (const float4*)b2f;

    {   void* a[] = {(void*)&pscores, (void*)&Wloc, (void*)&Wact};
        launch_pdl((const void*)k_selA, dim3(SELC, 21), dim3(256), a); }
    {   void* a[] = {(void*)&poff, (void*)&rois, (void*)&imgshape};
        launch_pdl((const void*)k_selB, dim3(1), dim3(32), a); }
    {   void* a[] = {(void*)&W1, (void*)&x};
        launch_pdl((const void*)k_gemv1, dim3(8, SPLIT1), dim3(128), a); }
    {   void* a[] = {(void*)&b1};
        launch_pdl((const void*)k_reduce1, dim3(256), dim3(256), a); }
    {   void* a[] = {(void*)&W2};
        launch_pdl((const void*)k_gemv2, dim3(8, SPLIT2), dim3(128), a); }
    {   void* a[] = {(void*)&b2, (void*)&Wloc, (void*)&Wact};
        launch_pdl((const void*)k_hred, dim3(HB), dim3(256), a); }
    {   void* a[] = {(void*)&bloc, (void*)&bact, (void*)&imgshape, (void*)&out};
        launch_pdl((const void*)k_final, dim3(1), dim3(256), a); }
}